// round 14
// baseline (speedup 1.0000x reference)
#include <cuda_runtime.h>
#include <cuda_fp16.h>
#include <cstdint>

#define M_TOT 65536      // B*N rows
#define DIMW  512        // DIM == INNER
#define WIN   128
#define NHEAD 8
#define DHEAD 64

// GEMM tiling (warp-MMA, mma.sync m16n8k16 fp16), 128 thr, warp tile 64x64
#define BM 128
#define BN 128
#define BK 64
#define NKC (DIMW / BK)
#define A_TILE_B (BM * 128)                     // 16 KB
#define B_TILE_B (BN * 128)                     // 16 KB
#define STAGE_B (A_TILE_B + B_TILE_B)           // 32 KB
#define NSTAGE 3
#define GEMM_SMEM (NSTAGE * STAGE_B)            // 96 KB

// ---------------- scratch (__device__ globals; no allocation allowed) -------
__device__ __half g_qh[(size_t)M_TOT * DIMW];
__device__ __half g_kh[(size_t)M_TOT * DIMW];
__device__ __half g_vh[(size_t)M_TOT * DIMW];
__device__ __half g_oh[(size_t)M_TOT * DIMW];

__device__ __half g_xh[(size_t)M_TOT * DIMW];
__device__ __half g_yh[(size_t)M_TOT * DIMW];

__device__ float2 g_stq[M_TOT];   // (mean, rstd) for q rows
__device__ float2 g_stk[M_TOT];   // (mean, rstd) for k rows

__device__ __half g_Wq[DIMW * DIMW];
__device__ __half g_Wk[DIMW * DIMW];
__device__ __half g_Wv[DIMW * DIMW];
__device__ __half g_Wo[DIMW * DIMW];

// ---------------- small asm helpers ------------------------------------------
__device__ __forceinline__ uint32_t smem_u32(const void* p) {
    uint32_t a;
    asm("{ .reg .u64 t; cvta.to.shared.u64 t, %1; cvt.u32.u64 %0, t; }"
        : "=r"(a) : "l"(p));
    return a;
}
__device__ __forceinline__ void cp16(uint32_t dst, const void* src) {
    asm volatile("cp.async.cg.shared.global [%0], [%1], 16;"
                 :: "r"(dst), "l"(src) : "memory");
}
__device__ __forceinline__ void cp_commit() {
    asm volatile("cp.async.commit_group;" ::: "memory");
}
template <int N>
__device__ __forceinline__ void cp_wait() {
    asm volatile("cp.async.wait_group %0;" :: "n"(N) : "memory");
}
__device__ __forceinline__ void ldsm4(uint32_t* r, uint32_t addr) {
    asm volatile("ldmatrix.sync.aligned.m8n8.x4.shared.b16 {%0,%1,%2,%3}, [%4];"
                 : "=r"(r[0]), "=r"(r[1]), "=r"(r[2]), "=r"(r[3]) : "r"(addr));
}
__device__ __forceinline__ void mma16816(float* d, const uint32_t* a,
                                         uint32_t b0, uint32_t b1) {
    asm volatile(
        "mma.sync.aligned.m16n8k16.row.col.f32.f16.f16.f32 "
        "{%0,%1,%2,%3}, {%4,%5,%6,%7}, {%8,%9}, {%0,%1,%2,%3};"
        : "+f"(d[0]), "+f"(d[1]), "+f"(d[2]), "+f"(d[3])
        : "r"(a[0]), "r"(a[1]), "r"(a[2]), "r"(a[3]), "r"(b0), "r"(b1));
}

// ---------------- fp32 -> fp16 convert (x, y activations) -------------------
__global__ __launch_bounds__(256) void cvt_kernel(const float4* __restrict__ in0,
                                                  const float4* __restrict__ in1,
                                                  uint2* __restrict__ o0,
                                                  uint2* __restrict__ o1, int n4)
{
    int i = blockIdx.x * blockDim.x + threadIdx.x;
    if (i >= n4) return;
    const float4* src = blockIdx.y ? in1 : in0;
    uint2* dst = blockIdx.y ? o1 : o0;
    float4 v = src[i];
    uint2 H;
    H.x = (uint32_t)__half_as_ushort(__float2half_rn(v.x)) |
          ((uint32_t)__half_as_ushort(__float2half_rn(v.y)) << 16);
    H.y = (uint32_t)__half_as_ushort(__float2half_rn(v.z)) |
          ((uint32_t)__half_as_ushort(__float2half_rn(v.w)) << 16);
    dst[i] = H;
}

// ---------------- fp32 -> fp16 round (weights, 4 at once) -------------------
__global__ __launch_bounds__(256) void wconv_kernel(const float4* __restrict__ w0,
                                                    const float4* __restrict__ w1,
                                                    const float4* __restrict__ w2,
                                                    const float4* __restrict__ w3,
                                                    uint2* __restrict__ o0,
                                                    uint2* __restrict__ o1,
                                                    uint2* __restrict__ o2,
                                                    uint2* __restrict__ o3, int n4)
{
    int i = blockIdx.x * blockDim.x + threadIdx.x;
    if (i >= n4) return;
    const float4* src = (blockIdx.y == 0) ? w0 : (blockIdx.y == 1) ? w1
                        : (blockIdx.y == 2) ? w2 : w3;
    uint2* dst = (blockIdx.y == 0) ? o0 : (blockIdx.y == 1) ? o1
                 : (blockIdx.y == 2) ? o2 : o3;
    float4 v = src[i];
    uint2 H;
    H.x = (uint32_t)__half_as_ushort(__float2half_rn(v.x)) |
          ((uint32_t)__half_as_ushort(__float2half_rn(v.y)) << 16);
    H.y = (uint32_t)__half_as_ushort(__float2half_rn(v.z)) |
          ((uint32_t)__half_as_ushort(__float2half_rn(v.w)) << 16);
    dst[i] = H;
}

// ---------------- fp16 warp-MMA GEMM (128 threads, warp tile 64x64) ----------
__device__ __forceinline__ void load_stage(uint32_t sbase,
    const __half* __restrict__ A, const __half* __restrict__ B,
    int m0, int n0, int kc, int tid)
{
    const int kcol = kc * BK;
    #pragma unroll
    for (int i = 0; i < 8; ++i) {               // A + B: 128 rows x 8 ch each
        int idx = tid + i * 128;
        int row = idx >> 3;
        int ch  = idx & 7;
        uint32_t soff = row * 128 + (((ch ^ (row & 7)) << 4));
        size_t ga = (size_t)(m0 + row) * DIMW + kcol + ch * 8;
        size_t gb = (size_t)(n0 + row) * DIMW + kcol + ch * 8;
        cp16(sbase + soff,            A + ga);
        cp16(sbase + A_TILE_B + soff, B + gb);
    }
    cp_commit();
}

// mode: 1 = fp32 + resid + bias, 2 = fp16 output
__device__ __forceinline__ void gemm_body(
    const __half* __restrict__ A, const __half* __restrict__ B,
    float* __restrict__ C, __half* __restrict__ C16,
    const float* __restrict__ Yadd, const float* __restrict__ bias, int mode)
{
    extern __shared__ char dsm[];
    const uint32_t sb = smem_u32(dsm);

    const int tid  = threadIdx.x;
    const int wid  = tid >> 5;
    const int lane = tid & 31;
    const int warp_m = wid >> 1;      // 0..1 -> 64 rows each
    const int warp_n = wid & 1;       // 0..1 -> 64 cols each
    const int m0 = blockIdx.y * BM;
    const int n0 = blockIdx.x * BN;

    float acc[4][8][4];
    #pragma unroll
    for (int a = 0; a < 4; ++a)
        #pragma unroll
        for (int b = 0; b < 8; ++b)
            #pragma unroll
            for (int c = 0; c < 4; ++c) acc[a][b][c] = 0.f;

    #pragma unroll
    for (int s = 0; s < NSTAGE - 1; ++s)
        load_stage(sb + s * STAGE_B, A, B, m0, n0, s, tid);

    const int frag_row = lane & 15;
    const int frag_ch  = lane >> 4;

    #pragma unroll 1
    for (int kc = 0; kc < NKC; ++kc) {
        cp_wait<NSTAGE - 2>();
        __syncthreads();

        const uint32_t st = sb + (kc % NSTAGE) * STAGE_B;
        const uint32_t sA = st;
        const uint32_t sB = st + A_TILE_B;

        // issue next-stage loads first (overlap with this chunk's MMAs)
        if (kc + NSTAGE - 1 < NKC)
            load_stage(sb + ((kc + NSTAGE - 1) % NSTAGE) * STAGE_B, A, B,
                       m0, n0, kc + NSTAGE - 1, tid);

        #pragma unroll
        for (int kk = 0; kk < 4; ++kk) {
            uint32_t ah[4][4];
            #pragma unroll
            for (int mi = 0; mi < 4; ++mi) {
                int row = warp_m * 64 + mi * 16 + frag_row;
                int ch  = kk * 2 + frag_ch;
                uint32_t off = row * 128 + (((ch ^ (row & 7)) << 4));
                ldsm4(ah[mi], sA + off);
            }
            uint32_t bh[4][4];
            #pragma unroll
            for (int ng = 0; ng < 4; ++ng) {
                int row = warp_n * 64 + ng * 16 + frag_row;
                int ch  = kk * 2 + frag_ch;
                uint32_t off = row * 128 + (((ch ^ (row & 7)) << 4));
                ldsm4(bh[ng], sB + off);
            }
            #pragma unroll
            for (int mi = 0; mi < 4; ++mi)
                #pragma unroll
                for (int ng = 0; ng < 4; ++ng) {
                    mma16816(acc[mi][ng * 2],     ah[mi], bh[ng][0], bh[ng][2]);
                    mma16816(acc[mi][ng * 2 + 1], ah[mi], bh[ng][1], bh[ng][3]);
                }
        }
    }

    const int erow = lane >> 2;
    const int ecol = (lane & 3) * 2;
    #pragma unroll
    for (int mi = 0; mi < 4; ++mi) {
        #pragma unroll
        for (int ni = 0; ni < 8; ++ni) {
            size_t r0 = (size_t)m0 + warp_m * 64 + mi * 16 + erow;
            int    c  = n0 + warp_n * 64 + ni * 8 + ecol;
            float2 v0 = make_float2(acc[mi][ni][0], acc[mi][ni][1]);
            float2 v1 = make_float2(acc[mi][ni][2], acc[mi][ni][3]);
            if (mode == 2) {
                __half2 h0 = __floats2half2_rn(v0.x, v0.y);
                __half2 h1 = __floats2half2_rn(v1.x, v1.y);
                *reinterpret_cast<__half2*>(C16 + r0 * DIMW + c)       = h0;
                *reinterpret_cast<__half2*>(C16 + (r0 + 8) * DIMW + c) = h1;
            } else {
                float2 y0 = *(const float2*)(Yadd + r0 * DIMW + c);
                float2 y1 = *(const float2*)(Yadd + (r0 + 8) * DIMW + c);
                float2 bv = *(const float2*)(bias + c);
                v0.x += y0.x + bv.x; v0.y += y0.y + bv.y;
                v1.x += y1.x + bv.x; v1.y += y1.y + bv.y;
                *(float2*)(C + r0 * DIMW + c)       = v0;
                *(float2*)(C + (r0 + 8) * DIMW + c) = v1;
            }
        }
    }
}

__global__ __launch_bounds__(128, 2) void qkv_gemm()
{
    if (blockIdx.z == 0)
        gemm_body(g_yh, g_Wq, nullptr, g_qh, nullptr, nullptr, 2);
    else if (blockIdx.z == 1)
        gemm_body(g_xh, g_Wk, nullptr, g_kh, nullptr, nullptr, 2);
    else
        gemm_body(g_xh, g_Wv, nullptr, g_vh, nullptr, nullptr, 2);
}

__global__ __launch_bounds__(128, 2) void out_gemm(const float* __restrict__ y,
                                                   const float* __restrict__ bout,
                                                   float* __restrict__ ynew)
{
    gemm_body(g_oh, g_Wo, ynew, nullptr, y, bout, 1);
}

// ---------------- LN row stats from fp16: one warp per row, shfl-only --------
__global__ __launch_bounds__(256) void stats_kernel()
{
    const __half* buf = blockIdx.y ? g_kh : g_qh;
    float2* st        = blockIdx.y ? g_stk : g_stq;
    const int row  = blockIdx.x * 8 + (threadIdx.x >> 5);
    const int lane = threadIdx.x & 31;
    const uint4* p = (const uint4*)(buf + (size_t)row * DIMW) + lane;

    float s = 0.f, sq = 0.f;
    #pragma unroll
    for (int i = 0; i < 2; ++i) {
        uint4 v = p[i * 32];
        #pragma unroll
        for (int w = 0; w < 4; ++w) {
            uint32_t raw = (&v.x)[w];
            float2 f = __half22float2(*reinterpret_cast<__half2*>(&raw));
            s  += f.x + f.y;
            sq += f.x * f.x + f.y * f.y;
        }
    }
    #pragma unroll
    for (int o = 16; o > 0; o >>= 1) {
        s  += __shfl_xor_sync(0xffffffffu, s,  o);
        sq += __shfl_xor_sync(0xffffffffu, sq, o);
    }
    if (lane == 0) {
        float mean = s * (1.f / 512.f);
        float var  = sq * (1.f / 512.f) - mean * mean;
        st[row] = make_float2(mean, rsqrtf(var + 1e-5f));
    }
}

// ---------------- tensor-core windowed attention, 2 blocks/SM ----------------
#define AQ_OFF   0
#define AK_OFF   16384
#define AVT_OFF  32768
#define AP_OFF   49152
#define AMX_OFF  81920
#define ASM_OFF  82944
#define ASTQ_OFF 83968
#define ASTK_OFF 84992
#define ASG_OFF  86016
#define ATTN_SMEM 87040
#define TSTRIDE  256

__global__ __launch_bounds__(256, 2) void attn_kernel(
    float* __restrict__ attn_out,
    const float* __restrict__ gq, const float* __restrict__ bq,
    const float* __restrict__ gk, const float* __restrict__ bk)
{
    extern __shared__ char asm_[];
    const uint32_t sb = smem_u32(asm_);
    float2* stq = (float2*)(asm_ + ASTQ_OFF);
    float2* stk = (float2*)(asm_ + ASTK_OFF);
    float*  sgq = (float*)(asm_ + ASG_OFF);
    float*  sbq = sgq + 64;
    float*  sgk = sgq + 128;
    float*  sbk = sgq + 192;
    float*  mxb = (float*)(asm_ + AMX_OFF);
    float*  smb = (float*)(asm_ + ASM_OFF);

    const int tid = threadIdx.x;
    const int bwh = blockIdx.x;        // bw*8 + h
    const int bw  = bwh >> 3;
    const int h   = bwh & 7;
    const size_t rowbase = (size_t)bw * WIN;
    const int coloff = h * DHEAD;

    if (tid < 128) {
        stq[tid] = g_stq[rowbase + tid];
        stk[tid] = g_stk[rowbase + tid];
    } else if (tid < 192) {
        int d = tid - 128;
        sgq[d] = gq[coloff + d] * 0.125f;
        sbq[d] = bq[coloff + d] * 0.125f;
        sgk[d] = gk[coloff + d];
        sbk[d] = bk[coloff + d];
    }
    __syncthreads();

    // ---- load: q,k (fp16 -> LN fp32 -> fp16, swizzled), v -> Vt transposed --
    #pragma unroll
    for (int it = 0; it < 8; ++it) {
        int idx = tid + it * 256;      // 0..2047
        int i   = idx >> 4;            // row 0..127
        int d4  = (idx & 15) << 2;     // 0..60
        size_t goff = (rowbase + i) * DIMW + coloff + d4;
        uint2 qraw = *(const uint2*)(g_qh + goff);
        uint2 kraw = *(const uint2*)(g_kh + goff);
        uint2 vraw = *(const uint2*)(g_vh + goff);

        float2 q01 = __half22float2(*reinterpret_cast<__half2*>(&qraw.x));
        float2 q23 = __half22float2(*reinterpret_cast<__half2*>(&qraw.y));
        float2 k01 = __half22float2(*reinterpret_cast<__half2*>(&kraw.x));
        float2 k23 = __half22float2(*reinterpret_cast<__half2*>(&kraw.y));

        float2 sq_ = stq[i];
        float2 sk_ = stk[i];
        __half2 qh0 = __floats2half2_rn(
            (q01.x - sq_.x) * sq_.y * sgq[d4 + 0] + sbq[d4 + 0],
            (q01.y - sq_.x) * sq_.y * sgq[d4 + 1] + sbq[d4 + 1]);
        __half2 qh1 = __floats2half2_rn(
            (q23.x - sq_.x) * sq_.y * sgq[d4 + 2] + sbq[d4 + 2],
            (q23.y - sq_.x) * sq_.y * sgq[d4 + 3] + sbq[d4 + 3]);
        __half2 kh0 = __floats2half2_rn(
            (k01.x - sk_.x) * sk_.y * sgk[d4 + 0] + sbk[d4 + 0],
            (k01.y - sk_.x) * sk_.y * sgk[d4 + 1] + sbk[d4 + 1]);
        __half2 kh1 = __floats2half2_rn(
            (k23.x - sk_.x) * sk_.y * sgk[d4 + 2] + sbk[d4 + 2],
            (k23.y - sk_.x) * sk_.y * sgk[d4 + 3] + sbk[d4 + 3]);

        uint32_t qkoff = i * 128 + (((d4 >> 3) ^ (i & 7)) << 4) + (d4 & 7) * 2;
        *(__half2*)(asm_ + AQ_OFF + qkoff)     = qh0;
        *(__half2*)(asm_ + AQ_OFF + qkoff + 4) = qh1;
        *(__half2*)(asm_ + AK_OFF + qkoff)     = kh0;
        *(__half2*)(asm_ + AK_OFF + qkoff + 4) = kh1;

        const __half* vh = reinterpret_cast<const __half*>(&vraw);
        #pragma unroll
        for (int w = 0; w < 4; ++w) {
            int d = d4 + w;
            uint32_t off = d * TSTRIDE + (((i >> 3) ^ (d & 7)) << 4) + (i & 7) * 2;
            *(__half*)(asm_ + AVT_OFF + off) = vh[w];
        }
    }
    __syncthreads();

    const int wid  = tid >> 5;
    const int lane = tid & 31;
    const int warp_m = wid >> 1;       // 0..3 -> 32 rows
    const int warp_n = wid & 1;        // 0..1 -> 64 cols (j or d)
    const int frag_row = lane & 15;
    const int frag_ch  = lane >> 4;
    const int erow = lane >> 2;
    const int equad = lane & 3;

    // ---- QK^T via HMMA ------------------------------------------------------
    float acc[2][8][4];
    #pragma unroll
    for (int a = 0; a < 2; ++a)
        #pragma unroll
        for (int b = 0; b < 8; ++b)
            #pragma unroll
            for (int c = 0; c < 4; ++c) acc[a][b][c] = 0.f;

    #pragma unroll
    for (int kk = 0; kk < 4; ++kk) {
        uint32_t ah[2][4];
        #pragma unroll
        for (int mi = 0; mi < 2; ++mi) {
            int row = warp_m * 32 + mi * 16 + frag_row;
            int ch  = kk * 2 + frag_ch;
            ldsm4(ah[mi], sb + AQ_OFF + row * 128 + (((ch ^ (row & 7)) << 4)));
        }
        uint32_t bh[4][4];
        #pragma unroll
        for (int ng = 0; ng < 4; ++ng) {
            int row = warp_n * 64 + ng * 16 + frag_row;
            int ch  = kk * 2 + frag_ch;
            ldsm4(bh[ng], sb + AK_OFF + row * 128 + (((ch ^ (row & 7)) << 4)));
        }
        #pragma unroll
        for (int mi = 0; mi < 2; ++mi)
            #pragma unroll
            for (int ng = 0; ng < 4; ++ng) {
                mma16816(acc[mi][ng * 2],     ah[mi], bh[ng][0], bh[ng][2]);
                mma16816(acc[mi][ng * 2 + 1], ah[mi], bh[ng][1], bh[ng][3]);
            }
    }

    // ---- softmax on fragments (fp32), cross-warp-pair via smem --------------
    #pragma unroll
    for (int mi = 0; mi < 2; ++mi)
        #pragma unroll
        for (int hh = 0; hh < 2; ++hh) {
            float m = -1e30f;
            #pragma unroll
            for (int ni = 0; ni < 8; ++ni) {
                m = fmaxf(m, acc[mi][ni][hh * 2]);
                m = fmaxf(m, acc[mi][ni][hh * 2 + 1]);
            }
            m = fmaxf(m, __shfl_xor_sync(0xffffffffu, m, 1));
            m = fmaxf(m, __shfl_xor_sync(0xffffffffu, m, 2));
            if (equad == 0) {
                int row = warp_m * 32 + mi * 16 + hh * 8 + erow;
                mxb[row * 2 + warp_n] = m;
            }
        }
    __syncthreads();

    #pragma unroll
    for (int mi = 0; mi < 2; ++mi)
        #pragma unroll
        for (int hh = 0; hh < 2; ++hh) {
            int row = warp_m * 32 + mi * 16 + hh * 8 + erow;
            float m = fmaxf(mxb[row * 2], mxb[row * 2 + 1]);
            float s = 0.f;
            #pragma unroll
            for (int ni = 0; ni < 8; ++ni) {
                float e0 = __expf(acc[mi][ni][hh * 2]     - m);
                float e1 = __expf(acc[mi][ni][hh * 2 + 1] - m);
                acc[mi][ni][hh * 2]     = e0;
                acc[mi][ni][hh * 2 + 1] = e1;
                s += e0 + e1;
            }
            s += __shfl_xor_sync(0xffffffffu, s, 1);
            s += __shfl_xor_sync(0xffffffffu, s, 2);
            if (equad == 0)
                smb[row * 2 + warp_n] = s;
        }
    __syncthreads();

    // ---- scale, write attn (fp32) + P (fp16 smem) ---------------------------
    const size_t abase = (size_t)bwh * WIN * WIN;
    #pragma unroll
    for (int mi = 0; mi < 2; ++mi)
        #pragma unroll
        for (int hh = 0; hh < 2; ++hh) {
            int row = warp_m * 32 + mi * 16 + hh * 8 + erow;
            float inv = 1.0f / (smb[row * 2] + smb[row * 2 + 1]);
            #pragma unroll
            for (int ni = 0; ni < 8; ++ni) {
                float p0 = acc[mi][ni][hh * 2]     * inv;
                float p1 = acc[mi][ni][hh * 2 + 1] * inv;
                int col = warp_n * 64 + ni * 8 + equad * 2;
                *(float2*)(attn_out + abase + (size_t)row * WIN + col) =
                    make_float2(p0, p1);
                uint32_t off = row * TSTRIDE +
                               (((col >> 3) ^ (row & 7)) << 4) + (col & 7) * 2;
                *(__half2*)(asm_ + AP_OFF + off) = __floats2half2_rn(p0, p1);
            }
        }
    __syncthreads();

    // ---- P @ V via HMMA ------------------------------------------------------
    float oac[2][4][4];
    #pragma unroll
    for (int a = 0; a < 2; ++a)
        #pragma unroll
        for (int b = 0; b < 4; ++b)
            #pragma unroll
            for (int c = 0; c < 4; ++c) oac[a][b][c] = 0.f;

    #pragma unroll
    for (int kk = 0; kk < 8; ++kk) {
        uint32_t ap[2][4];
        #pragma unroll
        for (int mi = 0; mi < 2; ++mi) {
            int row = warp_m * 32 + mi * 16 + frag_row;
            int ch  = kk * 2 + frag_ch;
            ldsm4(ap[mi], sb + AP_OFF + row * TSTRIDE +
                           (((ch ^ (row & 7)) << 4)));
        }
        uint32_t bv[2][4];
        #pragma unroll
        for (int ng = 0; ng < 2; ++ng) {
            int d  = warp_n * 32 + ng * 16 + frag_row;
            int ch = kk * 2 + frag_ch;
            ldsm4(bv[ng], sb + AVT_OFF + d * TSTRIDE +
                           (((ch ^ (d & 7)) << 4)));
        }
        #pragma unroll
        for (int mi = 0; mi < 2; ++mi)
            #pragma unroll
            for (int ng = 0; ng < 2; ++ng) {
                mma16816(oac[mi][ng * 2],     ap[mi], bv[ng][0], bv[ng][2]);
                mma16816(oac[mi][ng * 2 + 1], ap[mi], bv[ng][1], bv[ng][3]);
            }
    }

    // ---- write o (fp16) -----------------------------------------------------
    #pragma unroll
    for (int mi = 0; mi < 2; ++mi)
        #pragma unroll
        for (int ni = 0; ni < 4; ++ni) {
            int r0 = warp_m * 32 + mi * 16 + erow;
            int c  = coloff + warp_n * 32 + ni * 8 + equad * 2;
            size_t go0 = (rowbase + r0) * DIMW + c;
            size_t go1 = (rowbase + r0 + 8) * DIMW + c;
            *(__half2*)(g_oh + go0) = __floats2half2_rn(oac[mi][ni][0], oac[mi][ni][1]);
            *(__half2*)(g_oh + go1) = __floats2half2_rn(oac[mi][ni][2], oac[mi][ni][3]);
        }
}

// ---------------- launcher ---------------------------------------------------
extern "C" void kernel_launch(void* const* d_in, const int* in_sizes, int n_in,
                              void* d_out, int out_size)
{
    const float* x  = (const float*)d_in[0];
    const float* y  = (const float*)d_in[1];
    const float* Wq = (const float*)d_in[2];
    const float* gq = (const float*)d_in[3];
    const float* bq = (const float*)d_in[4];
    const float* Wk = (const float*)d_in[5];
    const float* gk = (const float*)d_in[6];
    const float* bk = (const float*)d_in[7];
    const float* Wv = (const float*)d_in[8];
    const float* Wo = (const float*)d_in[9];
    const float* bo = (const float*)d_in[10];

    float* ynew = (float*)d_out;
    float* attn = ynew + (size_t)M_TOT * DIMW;

    void *p_xh, *p_yh;
    void *p_wq, *p_wk, *p_wv, *p_wo;
    cudaGetSymbolAddress(&p_xh, g_xh);  cudaGetSymbolAddress(&p_yh, g_yh);
    cudaGetSymbolAddress(&p_wq, g_Wq);  cudaGetSymbolAddress(&p_wk, g_Wk);
    cudaGetSymbolAddress(&p_wv, g_Wv);  cudaGetSymbolAddress(&p_wo, g_Wo);

    cudaFuncSetAttribute(attn_kernel,
                         cudaFuncAttributeMaxDynamicSharedMemorySize, ATTN_SMEM);
    cudaFuncSetAttribute(qkv_gemm,
                         cudaFuncAttributeMaxDynamicSharedMemorySize, GEMM_SMEM);
    cudaFuncSetAttribute(out_gemm,
                         cudaFuncAttributeMaxDynamicSharedMemorySize, GEMM_SMEM);

    // 1) convert activations and weights to fp16
    const int n4_act = (M_TOT * DIMW) / 4;
    const int n4_w   = (DIMW * DIMW) / 4;
    cvt_kernel<<<dim3((n4_act + 255) / 256, 2), 256>>>(
        (const float4*)x, (const float4*)y, (uint2*)p_xh, (uint2*)p_yh, n4_act);
    wconv_kernel<<<dim3((n4_w + 255) / 256, 4), 256>>>(
        (const float4*)Wq, (const float4*)Wk, (const float4*)Wv, (const float4*)Wo,
        (uint2*)p_wq, (uint2*)p_wk, (uint2*)p_wv, (uint2*)p_wo, n4_w);

    // 2) q/k/v projections (warp-MMA fp16; q,k,v all written fp16)
    qkv_gemm<<<dim3(DIMW / BN, M_TOT / BM, 3), 128, GEMM_SMEM>>>();

    // 3) LN row stats for q, k (fp16 input)
    stats_kernel<<<dim3(M_TOT / 8, 2), 256>>>();

    // 4) tensor-core windowed attention -> attn (fp32) + fp16 o
    attn_kernel<<<4096, 256, ATTN_SMEM>>>(attn, gq, bq, gk, bk);

    // 5) final projection with residual epilogue
    out_gemm<<<dim3(DIMW / BN, M_TOT / BM), 128, GEMM_SMEM>>>(y, bo, ynew);
}

// round 15
// speedup vs baseline: 1.0185x; 1.0185x over previous
#include <cuda_runtime.h>
#include <cuda_fp16.h>
#include <cstdint>

#define M_TOT 65536      // B*N rows
#define DIMW  512        // DIM == INNER
#define WIN   128
#define NHEAD 8
#define DHEAD 64

// GEMM tiling (warp-MMA, mma.sync m16n8k16 fp16), 256 thr, 2 CTA/SM
#define BM 128
#define BN 128
#define BK 64
#define NKC (DIMW / BK)
#define A_TILE_B (BM * 128)                     // 16 KB
#define B_TILE_B (BN * 128)                     // 16 KB
#define STAGE_B (A_TILE_B + B_TILE_B)           // 32 KB
#define NSTAGE 3
#define GEMM_SMEM (NSTAGE * STAGE_B)            // 96 KB

// ---------------- scratch (__device__ globals; no allocation allowed) -------
__device__ __half g_qh[(size_t)M_TOT * DIMW];
__device__ __half g_kh[(size_t)M_TOT * DIMW];
__device__ __half g_vh[(size_t)M_TOT * DIMW];
__device__ __half g_oh[(size_t)M_TOT * DIMW];

__device__ __half g_xh[(size_t)M_TOT * DIMW];
__device__ __half g_yh[(size_t)M_TOT * DIMW];

// per-row LN partial sums: 8 slots/row (4 n-tiles x 2 warp_n), (sum, sumsq)
__device__ float2 g_psq[(size_t)M_TOT * 8];
__device__ float2 g_psk[(size_t)M_TOT * 8];

__device__ __half g_Wq[DIMW * DIMW];
__device__ __half g_Wk[DIMW * DIMW];
__device__ __half g_Wv[DIMW * DIMW];
__device__ __half g_Wo[DIMW * DIMW];

// ---------------- small asm helpers ------------------------------------------
__device__ __forceinline__ uint32_t smem_u32(const void* p) {
    uint32_t a;
    asm("{ .reg .u64 t; cvta.to.shared.u64 t, %1; cvt.u32.u64 %0, t; }"
        : "=r"(a) : "l"(p));
    return a;
}
__device__ __forceinline__ void cp16(uint32_t dst, const void* src) {
    asm volatile("cp.async.cg.shared.global [%0], [%1], 16;"
                 :: "r"(dst), "l"(src) : "memory");
}
__device__ __forceinline__ void cp_commit() {
    asm volatile("cp.async.commit_group;" ::: "memory");
}
template <int N>
__device__ __forceinline__ void cp_wait() {
    asm volatile("cp.async.wait_group %0;" :: "n"(N) : "memory");
}
__device__ __forceinline__ void ldsm4(uint32_t* r, uint32_t addr) {
    asm volatile("ldmatrix.sync.aligned.m8n8.x4.shared.b16 {%0,%1,%2,%3}, [%4];"
                 : "=r"(r[0]), "=r"(r[1]), "=r"(r[2]), "=r"(r[3]) : "r"(addr));
}
__device__ __forceinline__ void mma16816(float* d, const uint32_t* a,
                                         uint32_t b0, uint32_t b1) {
    asm volatile(
        "mma.sync.aligned.m16n8k16.row.col.f32.f16.f16.f32 "
        "{%0,%1,%2,%3}, {%4,%5,%6,%7}, {%8,%9}, {%0,%1,%2,%3};"
        : "+f"(d[0]), "+f"(d[1]), "+f"(d[2]), "+f"(d[3])
        : "r"(a[0]), "r"(a[1]), "r"(a[2]), "r"(a[3]), "r"(b0), "r"(b1));
}

// ---------------- fp32 -> fp16 convert (x, y activations) -------------------
__global__ __launch_bounds__(256) void cvt_kernel(const float4* __restrict__ in0,
                                                  const float4* __restrict__ in1,
                                                  uint2* __restrict__ o0,
                                                  uint2* __restrict__ o1, int n4)
{
    int i = blockIdx.x * blockDim.x + threadIdx.x;
    if (i >= n4) return;
    const float4* src = blockIdx.y ? in1 : in0;
    uint2* dst = blockIdx.y ? o1 : o0;
    float4 v = src[i];
    uint2 H;
    H.x = (uint32_t)__half_as_ushort(__float2half_rn(v.x)) |
          ((uint32_t)__half_as_ushort(__float2half_rn(v.y)) << 16);
    H.y = (uint32_t)__half_as_ushort(__float2half_rn(v.z)) |
          ((uint32_t)__half_as_ushort(__float2half_rn(v.w)) << 16);
    dst[i] = H;
}

// ---------------- fp32 -> fp16 round (weights, 4 at once) -------------------
__global__ __launch_bounds__(256) void wconv_kernel(const float4* __restrict__ w0,
                                                    const float4* __restrict__ w1,
                                                    const float4* __restrict__ w2,
                                                    const float4* __restrict__ w3,
                                                    uint2* __restrict__ o0,
                                                    uint2* __restrict__ o1,
                                                    uint2* __restrict__ o2,
                                                    uint2* __restrict__ o3, int n4)
{
    int i = blockIdx.x * blockDim.x + threadIdx.x;
    if (i >= n4) return;
    const float4* src = (blockIdx.y == 0) ? w0 : (blockIdx.y == 1) ? w1
                        : (blockIdx.y == 2) ? w2 : w3;
    uint2* dst = (blockIdx.y == 0) ? o0 : (blockIdx.y == 1) ? o1
                 : (blockIdx.y == 2) ? o2 : o3;
    float4 v = src[i];
    uint2 H;
    H.x = (uint32_t)__half_as_ushort(__float2half_rn(v.x)) |
          ((uint32_t)__half_as_ushort(__float2half_rn(v.y)) << 16);
    H.y = (uint32_t)__half_as_ushort(__float2half_rn(v.z)) |
          ((uint32_t)__half_as_ushort(__float2half_rn(v.w)) << 16);
    dst[i] = H;
}

// ---------------- fp16 warp-MMA GEMM (256 threads, BM128 x BN128) ------------
__device__ __forceinline__ void load_stage(uint32_t sbase,
    const __half* __restrict__ A, const __half* __restrict__ B,
    int m0, int n0, int kc, int tid)
{
    const int kcol = kc * BK;
    #pragma unroll
    for (int i = 0; i < 4; ++i) {               // A + B: 128 rows x 8 ch
        int idx = tid + i * 256;
        int row = idx >> 3;
        int ch  = idx & 7;
        uint32_t soff = row * 128 + (((ch ^ (row & 7)) << 4));
        size_t ga = (size_t)(m0 + row) * DIMW + kcol + ch * 8;
        size_t gb = (size_t)(n0 + row) * DIMW + kcol + ch * 8;
        cp16(sbase + soff,            A + ga);
        cp16(sbase + A_TILE_B + soff, B + gb);
    }
    cp_commit();
}

// mode: 1 = fp32 + resid + bias, 2 = fp16 output (psum optional LN partials)
__device__ __forceinline__ void gemm_body(
    const __half* __restrict__ A, const __half* __restrict__ B,
    float* __restrict__ C, __half* __restrict__ C16,
    const float* __restrict__ Yadd, const float* __restrict__ bias, int mode,
    float2* __restrict__ psum)
{
    extern __shared__ char dsm[];
    const uint32_t sb = smem_u32(dsm);

    const int tid  = threadIdx.x;
    const int wid  = tid >> 5;
    const int lane = tid & 31;
    const int warp_m = wid >> 1;      // 0..3 -> 32 rows each
    const int warp_n = wid & 1;       // 0..1 -> 64 cols each
    const int m0 = blockIdx.y * BM;
    const int n0 = blockIdx.x * BN;

    float acc[2][8][4];
    #pragma unroll
    for (int a = 0; a < 2; ++a)
        #pragma unroll
        for (int b = 0; b < 8; ++b)
            #pragma unroll
            for (int c = 0; c < 4; ++c) acc[a][b][c] = 0.f;

    #pragma unroll
    for (int s = 0; s < NSTAGE - 1; ++s)
        load_stage(sb + s * STAGE_B, A, B, m0, n0, s, tid);

    const int frag_row = lane & 15;
    const int frag_ch  = lane >> 4;

    #pragma unroll 1
    for (int kc = 0; kc < NKC; ++kc) {
        cp_wait<NSTAGE - 2>();
        __syncthreads();

        const uint32_t st = sb + (kc % NSTAGE) * STAGE_B;
        const uint32_t sA = st;
        const uint32_t sB = st + A_TILE_B;

        // issue next-stage loads first (overlap with this chunk's MMAs)
        if (kc + NSTAGE - 1 < NKC)
            load_stage(sb + ((kc + NSTAGE - 1) % NSTAGE) * STAGE_B, A, B,
                       m0, n0, kc + NSTAGE - 1, tid);

        #pragma unroll
        for (int kk = 0; kk < 4; ++kk) {
            uint32_t ah[2][4];
            #pragma unroll
            for (int mi = 0; mi < 2; ++mi) {
                int row = warp_m * 32 + mi * 16 + frag_row;
                int ch  = kk * 2 + frag_ch;
                uint32_t off = row * 128 + (((ch ^ (row & 7)) << 4));
                ldsm4(ah[mi], sA + off);
            }
            uint32_t bh[4][4];
            #pragma unroll
            for (int ng = 0; ng < 4; ++ng) {
                int row = warp_n * 64 + ng * 16 + frag_row;
                int ch  = kk * 2 + frag_ch;
                uint32_t off = row * 128 + (((ch ^ (row & 7)) << 4));
                ldsm4(bh[ng], sB + off);
            }
            #pragma unroll
            for (int mi = 0; mi < 2; ++mi)
                #pragma unroll
                for (int ng = 0; ng < 4; ++ng) {
                    mma16816(acc[mi][ng * 2],     ah[mi], bh[ng][0], bh[ng][2]);
                    mma16816(acc[mi][ng * 2 + 1], ah[mi], bh[ng][1], bh[ng][3]);
                }
        }
    }

    const int erow = lane >> 2;
    const int ecol = (lane & 3) * 2;
    #pragma unroll
    for (int mi = 0; mi < 2; ++mi) {
        float s0 = 0.f, q0 = 0.f, s1 = 0.f, q1 = 0.f;
        #pragma unroll
        for (int ni = 0; ni < 8; ++ni) {
            size_t r0 = (size_t)m0 + warp_m * 32 + mi * 16 + erow;
            int    c  = n0 + warp_n * 64 + ni * 8 + ecol;
            float2 v0 = make_float2(acc[mi][ni][0], acc[mi][ni][1]);
            float2 v1 = make_float2(acc[mi][ni][2], acc[mi][ni][3]);
            if (mode == 2) {
                __half2 h0 = __floats2half2_rn(v0.x, v0.y);
                __half2 h1 = __floats2half2_rn(v1.x, v1.y);
                *reinterpret_cast<__half2*>(C16 + r0 * DIMW + c)       = h0;
                *reinterpret_cast<__half2*>(C16 + (r0 + 8) * DIMW + c) = h1;
                if (psum) {
                    float2 f0 = __half22float2(h0);
                    float2 f1 = __half22float2(h1);
                    s0 += f0.x + f0.y; q0 += f0.x * f0.x + f0.y * f0.y;
                    s1 += f1.x + f1.y; q1 += f1.x * f1.x + f1.y * f1.y;
                }
            } else {
                float2 y0 = *(const float2*)(Yadd + r0 * DIMW + c);
                float2 y1 = *(const float2*)(Yadd + (r0 + 8) * DIMW + c);
                float2 bv = *(const float2*)(bias + c);
                v0.x += y0.x + bv.x; v0.y += y0.y + bv.y;
                v1.x += y1.x + bv.x; v1.y += y1.y + bv.y;
                *(float2*)(C + r0 * DIMW + c)       = v0;
                *(float2*)(C + (r0 + 8) * DIMW + c) = v1;
            }
        }
        if (mode == 2 && psum) {
            s0 += __shfl_xor_sync(0xffffffffu, s0, 1);
            s0 += __shfl_xor_sync(0xffffffffu, s0, 2);
            q0 += __shfl_xor_sync(0xffffffffu, q0, 1);
            q0 += __shfl_xor_sync(0xffffffffu, q0, 2);
            s1 += __shfl_xor_sync(0xffffffffu, s1, 1);
            s1 += __shfl_xor_sync(0xffffffffu, s1, 2);
            q1 += __shfl_xor_sync(0xffffffffu, q1, 1);
            q1 += __shfl_xor_sync(0xffffffffu, q1, 2);
            if ((lane & 3) == 0) {
                size_t row = (size_t)m0 + warp_m * 32 + mi * 16 + erow;
                int slot = blockIdx.x * 2 + warp_n;
                psum[row * 8 + slot]       = make_float2(s0, q0);
                psum[(row + 8) * 8 + slot] = make_float2(s1, q1);
            }
        }
    }
}

__global__ __launch_bounds__(256, 2) void qkv_gemm()
{
    if (blockIdx.z == 0)
        gemm_body(g_yh, g_Wq, nullptr, g_qh, nullptr, nullptr, 2, g_psq);
    else if (blockIdx.z == 1)
        gemm_body(g_xh, g_Wk, nullptr, g_kh, nullptr, nullptr, 2, g_psk);
    else
        gemm_body(g_xh, g_Wv, nullptr, g_vh, nullptr, nullptr, 2, nullptr);
}

__global__ __launch_bounds__(256, 2) void out_gemm(const float* __restrict__ y,
                                                   const float* __restrict__ bout,
                                                   float* __restrict__ ynew)
{
    gemm_body(g_oh, g_Wo, ynew, nullptr, y, bout, 1, nullptr);
}

// ---------------- tensor-core windowed attention, 2 blocks/SM ----------------
#define AQ_OFF   0
#define AK_OFF   16384
#define AVT_OFF  32768
#define AP_OFF   49152
#define AMX_OFF  81920
#define ASM_OFF  82944
#define ASTQ_OFF 83968
#define ASTK_OFF 84992
#define ASG_OFF  86016
#define ATTN_SMEM 87040
#define TSTRIDE  256

__global__ __launch_bounds__(256, 2) void attn_kernel(
    float* __restrict__ attn_out,
    const float* __restrict__ gq, const float* __restrict__ bq,
    const float* __restrict__ gk, const float* __restrict__ bk)
{
    extern __shared__ char asm_[];
    const uint32_t sb = smem_u32(asm_);
    float2* stq = (float2*)(asm_ + ASTQ_OFF);
    float2* stk = (float2*)(asm_ + ASTK_OFF);
    float*  sgq = (float*)(asm_ + ASG_OFF);
    float*  sbq = sgq + 64;
    float*  sgk = sgq + 128;
    float*  sbk = sgq + 192;
    float*  mxb = (float*)(asm_ + AMX_OFF);
    float*  smb = (float*)(asm_ + ASM_OFF);

    const int tid = threadIdx.x;
    const int bwh = blockIdx.x;        // bw*8 + h
    const int bw  = bwh >> 3;
    const int h   = bwh & 7;
    const size_t rowbase = (size_t)bw * WIN;
    const int coloff = h * DHEAD;

    if (tid < 128) {
        // combine 8 per-row LN partials -> (mean, rstd)
        const float2* pq = g_psq + (rowbase + tid) * 8;
        const float2* pk = g_psk + (rowbase + tid) * 8;
        float s = 0.f, q = 0.f;
        #pragma unroll
        for (int p = 0; p < 8; ++p) { float2 v = pq[p]; s += v.x; q += v.y; }
        float mean = s * (1.f / 512.f);
        float var  = q * (1.f / 512.f) - mean * mean;
        stq[tid] = make_float2(mean, rsqrtf(var + 1e-5f));
        s = 0.f; q = 0.f;
        #pragma unroll
        for (int p = 0; p < 8; ++p) { float2 v = pk[p]; s += v.x; q += v.y; }
        mean = s * (1.f / 512.f);
        var  = q * (1.f / 512.f) - mean * mean;
        stk[tid] = make_float2(mean, rsqrtf(var + 1e-5f));
    } else if (tid < 192) {
        int d = tid - 128;
        sgq[d] = gq[coloff + d] * 0.125f;
        sbq[d] = bq[coloff + d] * 0.125f;
        sgk[d] = gk[coloff + d];
        sbk[d] = bk[coloff + d];
    }
    __syncthreads();

    // ---- load: q,k (fp16 -> LN fp32 -> fp16, swizzled), v -> Vt transposed --
    #pragma unroll
    for (int it = 0; it < 8; ++it) {
        int idx = tid + it * 256;      // 0..2047
        int i   = idx >> 4;            // row 0..127
        int d4  = (idx & 15) << 2;     // 0..60
        size_t goff = (rowbase + i) * DIMW + coloff + d4;
        uint2 qraw = *(const uint2*)(g_qh + goff);
        uint2 kraw = *(const uint2*)(g_kh + goff);
        uint2 vraw = *(const uint2*)(g_vh + goff);

        float2 q01 = __half22float2(*reinterpret_cast<__half2*>(&qraw.x));
        float2 q23 = __half22float2(*reinterpret_cast<__half2*>(&qraw.y));
        float2 k01 = __half22float2(*reinterpret_cast<__half2*>(&kraw.x));
        float2 k23 = __half22float2(*reinterpret_cast<__half2*>(&kraw.y));

        float2 sq_ = stq[i];
        float2 sk_ = stk[i];
        __half2 qh0 = __floats2half2_rn(
            (q01.x - sq_.x) * sq_.y * sgq[d4 + 0] + sbq[d4 + 0],
            (q01.y - sq_.x) * sq_.y * sgq[d4 + 1] + sbq[d4 + 1]);
        __half2 qh1 = __floats2half2_rn(
            (q23.x - sq_.x) * sq_.y * sgq[d4 + 2] + sbq[d4 + 2],
            (q23.y - sq_.x) * sq_.y * sgq[d4 + 3] + sbq[d4 + 3]);
        __half2 kh0 = __floats2half2_rn(
            (k01.x - sk_.x) * sk_.y * sgk[d4 + 0] + sbk[d4 + 0],
            (k01.y - sk_.x) * sk_.y * sgk[d4 + 1] + sbk[d4 + 1]);
        __half2 kh1 = __floats2half2_rn(
            (k23.x - sk_.x) * sk_.y * sgk[d4 + 2] + sbk[d4 + 2],
            (k23.y - sk_.x) * sk_.y * sgk[d4 + 3] + sbk[d4 + 3]);

        uint32_t qkoff = i * 128 + (((d4 >> 3) ^ (i & 7)) << 4) + (d4 & 7) * 2;
        *(__half2*)(asm_ + AQ_OFF + qkoff)     = qh0;
        *(__half2*)(asm_ + AQ_OFF + qkoff + 4) = qh1;
        *(__half2*)(asm_ + AK_OFF + qkoff)     = kh0;
        *(__half2*)(asm_ + AK_OFF + qkoff + 4) = kh1;

        const __half* vh = reinterpret_cast<const __half*>(&vraw);
        #pragma unroll
        for (int w = 0; w < 4; ++w) {
            int d = d4 + w;
            uint32_t off = d * TSTRIDE + (((i >> 3) ^ (d & 7)) << 4) + (i & 7) * 2;
            *(__half*)(asm_ + AVT_OFF + off) = vh[w];
        }
    }
    __syncthreads();

    const int wid  = tid >> 5;
    const int lane = tid & 31;
    const int warp_m = wid >> 1;       // 0..3 -> 32 rows
    const int warp_n = wid & 1;        // 0..1 -> 64 cols (j or d)
    const int frag_row = lane & 15;
    const int frag_ch  = lane >> 4;
    const int erow = lane >> 2;
    const int equad = lane & 3;

    // ---- QK^T via HMMA ------------------------------------------------------
    float acc[2][8][4];
    #pragma unroll
    for (int a = 0; a < 2; ++a)
        #pragma unroll
        for (int b = 0; b < 8; ++b)
            #pragma unroll
            for (int c = 0; c < 4; ++c) acc[a][b][c] = 0.f;

    #pragma unroll
    for (int kk = 0; kk < 4; ++kk) {
        uint32_t ah[2][4];
        #pragma unroll
        for (int mi = 0; mi < 2; ++mi) {
            int row = warp_m * 32 + mi * 16 + frag_row;
            int ch  = kk * 2 + frag_ch;
            ldsm4(ah[mi], sb + AQ_OFF + row * 128 + (((ch ^ (row & 7)) << 4)));
        }
        uint32_t bh[4][4];
        #pragma unroll
        for (int ng = 0; ng < 4; ++ng) {
            int row = warp_n * 64 + ng * 16 + frag_row;
            int ch  = kk * 2 + frag_ch;
            ldsm4(bh[ng], sb + AK_OFF + row * 128 + (((ch ^ (row & 7)) << 4)));
        }
        #pragma unroll
        for (int mi = 0; mi < 2; ++mi)
            #pragma unroll
            for (int ng = 0; ng < 4; ++ng) {
                mma16816(acc[mi][ng * 2],     ah[mi], bh[ng][0], bh[ng][2]);
                mma16816(acc[mi][ng * 2 + 1], ah[mi], bh[ng][1], bh[ng][3]);
            }
    }

    // ---- softmax on fragments (fp32), cross-warp-pair via smem --------------
    #pragma unroll
    for (int mi = 0; mi < 2; ++mi)
        #pragma unroll
        for (int hh = 0; hh < 2; ++hh) {
            float m = -1e30f;
            #pragma unroll
            for (int ni = 0; ni < 8; ++ni) {
                m = fmaxf(m, acc[mi][ni][hh * 2]);
                m = fmaxf(m, acc[mi][ni][hh * 2 + 1]);
            }
            m = fmaxf(m, __shfl_xor_sync(0xffffffffu, m, 1));
            m = fmaxf(m, __shfl_xor_sync(0xffffffffu, m, 2));
            if (equad == 0) {
                int row = warp_m * 32 + mi * 16 + hh * 8 + erow;
                mxb[row * 2 + warp_n] = m;
            }
        }
    __syncthreads();

    #pragma unroll
    for (int mi = 0; mi < 2; ++mi)
        #pragma unroll
        for (int hh = 0; hh < 2; ++hh) {
            int row = warp_m * 32 + mi * 16 + hh * 8 + erow;
            float m = fmaxf(mxb[row * 2], mxb[row * 2 + 1]);
            float s = 0.f;
            #pragma unroll
            for (int ni = 0; ni < 8; ++ni) {
                float e0 = __expf(acc[mi][ni][hh * 2]     - m);
                float e1 = __expf(acc[mi][ni][hh * 2 + 1] - m);
                acc[mi][ni][hh * 2]     = e0;
                acc[mi][ni][hh * 2 + 1] = e1;
                s += e0 + e1;
            }
            s += __shfl_xor_sync(0xffffffffu, s, 1);
            s += __shfl_xor_sync(0xffffffffu, s, 2);
            if (equad == 0)
                smb[row * 2 + warp_n] = s;
        }
    __syncthreads();

    // ---- scale, write attn (fp32) + P (fp16 smem) ---------------------------
    const size_t abase = (size_t)bwh * WIN * WIN;
    #pragma unroll
    for (int mi = 0; mi < 2; ++mi)
        #pragma unroll
        for (int hh = 0; hh < 2; ++hh) {
            int row = warp_m * 32 + mi * 16 + hh * 8 + erow;
            float inv = 1.0f / (smb[row * 2] + smb[row * 2 + 1]);
            #pragma unroll
            for (int ni = 0; ni < 8; ++ni) {
                float p0 = acc[mi][ni][hh * 2]     * inv;
                float p1 = acc[mi][ni][hh * 2 + 1] * inv;
                int col = warp_n * 64 + ni * 8 + equad * 2;
                *(float2*)(attn_out + abase + (size_t)row * WIN + col) =
                    make_float2(p0, p1);
                uint32_t off = row * TSTRIDE +
                               (((col >> 3) ^ (row & 7)) << 4) + (col & 7) * 2;
                *(__half2*)(asm_ + AP_OFF + off) = __floats2half2_rn(p0, p1);
            }
        }
    __syncthreads();

    // ---- P @ V via HMMA ------------------------------------------------------
    float oac[2][4][4];
    #pragma unroll
    for (int a = 0; a < 2; ++a)
        #pragma unroll
        for (int b = 0; b < 4; ++b)
            #pragma unroll
            for (int c = 0; c < 4; ++c) oac[a][b][c] = 0.f;

    #pragma unroll
    for (int kk = 0; kk < 8; ++kk) {
        uint32_t ap[2][4];
        #pragma unroll
        for (int mi = 0; mi < 2; ++mi) {
            int row = warp_m * 32 + mi * 16 + frag_row;
            int ch  = kk * 2 + frag_ch;
            ldsm4(ap[mi], sb + AP_OFF + row * TSTRIDE +
                           (((ch ^ (row & 7)) << 4)));
        }
        uint32_t bv[2][4];
        #pragma unroll
        for (int ng = 0; ng < 2; ++ng) {
            int d  = warp_n * 32 + ng * 16 + frag_row;
            int ch = kk * 2 + frag_ch;
            ldsm4(bv[ng], sb + AVT_OFF + d * TSTRIDE +
                           (((ch ^ (d & 7)) << 4)));
        }
        #pragma unroll
        for (int mi = 0; mi < 2; ++mi)
            #pragma unroll
            for (int ng = 0; ng < 2; ++ng) {
                mma16816(oac[mi][ng * 2],     ap[mi], bv[ng][0], bv[ng][2]);
                mma16816(oac[mi][ng * 2 + 1], ap[mi], bv[ng][1], bv[ng][3]);
            }
    }

    // ---- write o (fp16) -----------------------------------------------------
    #pragma unroll
    for (int mi = 0; mi < 2; ++mi)
        #pragma unroll
        for (int ni = 0; ni < 4; ++ni) {
            int r0 = warp_m * 32 + mi * 16 + erow;
            int c  = coloff + warp_n * 32 + ni * 8 + equad * 2;
            size_t go0 = (rowbase + r0) * DIMW + c;
            size_t go1 = (rowbase + r0 + 8) * DIMW + c;
            *(__half2*)(g_oh + go0) = __floats2half2_rn(oac[mi][ni][0], oac[mi][ni][1]);
            *(__half2*)(g_oh + go1) = __floats2half2_rn(oac[mi][ni][2], oac[mi][ni][3]);
        }
}

// ---------------- launcher ---------------------------------------------------
extern "C" void kernel_launch(void* const* d_in, const int* in_sizes, int n_in,
                              void* d_out, int out_size)
{
    const float* x  = (const float*)d_in[0];
    const float* y  = (const float*)d_in[1];
    const float* Wq = (const float*)d_in[2];
    const float* gq = (const float*)d_in[3];
    const float* bq = (const float*)d_in[4];
    const float* Wk = (const float*)d_in[5];
    const float* gk = (const float*)d_in[6];
    const float* bk = (const float*)d_in[7];
    const float* Wv = (const float*)d_in[8];
    const float* Wo = (const float*)d_in[9];
    const float* bo = (const float*)d_in[10];

    float* ynew = (float*)d_out;
    float* attn = ynew + (size_t)M_TOT * DIMW;

    void *p_xh, *p_yh;
    void *p_wq, *p_wk, *p_wv, *p_wo;
    cudaGetSymbolAddress(&p_xh, g_xh);  cudaGetSymbolAddress(&p_yh, g_yh);
    cudaGetSymbolAddress(&p_wq, g_Wq);  cudaGetSymbolAddress(&p_wk, g_Wk);
    cudaGetSymbolAddress(&p_wv, g_Wv);  cudaGetSymbolAddress(&p_wo, g_Wo);

    cudaFuncSetAttribute(attn_kernel,
                         cudaFuncAttributeMaxDynamicSharedMemorySize, ATTN_SMEM);
    cudaFuncSetAttribute(qkv_gemm,
                         cudaFuncAttributeMaxDynamicSharedMemorySize, GEMM_SMEM);
    cudaFuncSetAttribute(out_gemm,
                         cudaFuncAttributeMaxDynamicSharedMemorySize, GEMM_SMEM);

    // 1) convert activations and weights to fp16
    const int n4_act = (M_TOT * DIMW) / 4;
    const int n4_w   = (DIMW * DIMW) / 4;
    cvt_kernel<<<dim3((n4_act + 255) / 256, 2), 256>>>(
        (const float4*)x, (const float4*)y, (uint2*)p_xh, (uint2*)p_yh, n4_act);
    wconv_kernel<<<dim3((n4_w + 255) / 256, 4), 256>>>(
        (const float4*)Wq, (const float4*)Wk, (const float4*)Wv, (const float4*)Wo,
        (uint2*)p_wq, (uint2*)p_wk, (uint2*)p_wv, (uint2*)p_wo, n4_w);

    // 2) q/k/v projections (fp16 warp-MMA; LN partial sums fused in epilogue)
    qkv_gemm<<<dim3(DIMW / BN, M_TOT / BM, 3), 256, GEMM_SMEM>>>();

    // 3) tensor-core windowed attention (stats combined from partials)
    attn_kernel<<<4096, 256, ATTN_SMEM>>>(attn, gq, bq, gk, bk);

    // 4) final projection with residual epilogue
    out_gemm<<<dim3(DIMW / BN, M_TOT / BM), 256, GEMM_SMEM>>>(y, bo, ynew);
}

// round 16
// speedup vs baseline: 1.0341x; 1.0153x over previous
#include <cuda_runtime.h>
#include <cuda_fp16.h>
#include <cstdint>

#define M_TOT 65536      // B*N rows
#define DIMW  512        // DIM == INNER
#define WIN   128
#define NHEAD 8
#define DHEAD 64

// GEMM tiling (warp-MMA, mma.sync m16n8k16 fp16), 256 thr, 2 CTA/SM
#define BM 128
#define BN 128
#define BK 64
#define NKC (DIMW / BK)
#define A_TILE_B (BM * 128)                     // 16 KB
#define B_TILE_B (BN * 128)                     // 16 KB
#define STAGE_B (A_TILE_B + B_TILE_B)           // 32 KB
#define NSTAGE 3
#define GEMM_SMEM (NSTAGE * STAGE_B)            // 96 KB

// ---------------- scratch (__device__ globals; no allocation allowed) -------
__device__ __half g_qh[(size_t)M_TOT * DIMW];
__device__ __half g_kh[(size_t)M_TOT * DIMW];
__device__ __half g_vh[(size_t)M_TOT * DIMW];
__device__ __half g_oh[(size_t)M_TOT * DIMW];

__device__ __half g_xh[(size_t)M_TOT * DIMW];
__device__ __half g_yh[(size_t)M_TOT * DIMW];

// per-row LN partial sums: 8 slots/row (4 n-tiles x 2 warp_n), (sum, sumsq)
__device__ float2 g_psq[(size_t)M_TOT * 8];
__device__ float2 g_psk[(size_t)M_TOT * 8];

__device__ __half g_Wq[DIMW * DIMW];
__device__ __half g_Wk[DIMW * DIMW];
__device__ __half g_Wv[DIMW * DIMW];
__device__ __half g_Wo[DIMW * DIMW];

// ---------------- small asm helpers ------------------------------------------
__device__ __forceinline__ uint32_t smem_u32(const void* p) {
    uint32_t a;
    asm("{ .reg .u64 t; cvta.to.shared.u64 t, %1; cvt.u32.u64 %0, t; }"
        : "=r"(a) : "l"(p));
    return a;
}
__device__ __forceinline__ void cp16(uint32_t dst, const void* src) {
    asm volatile("cp.async.cg.shared.global [%0], [%1], 16;"
                 :: "r"(dst), "l"(src) : "memory");
}
__device__ __forceinline__ void cp_commit() {
    asm volatile("cp.async.commit_group;" ::: "memory");
}
template <int N>
__device__ __forceinline__ void cp_wait() {
    asm volatile("cp.async.wait_group %0;" :: "n"(N) : "memory");
}
__device__ __forceinline__ void ldsm4(uint32_t* r, uint32_t addr) {
    asm volatile("ldmatrix.sync.aligned.m8n8.x4.shared.b16 {%0,%1,%2,%3}, [%4];"
                 : "=r"(r[0]), "=r"(r[1]), "=r"(r[2]), "=r"(r[3]) : "r"(addr));
}
__device__ __forceinline__ void mma16816(float* d, const uint32_t* a,
                                         uint32_t b0, uint32_t b1) {
    asm volatile(
        "mma.sync.aligned.m16n8k16.row.col.f32.f16.f16.f32 "
        "{%0,%1,%2,%3}, {%4,%5,%6,%7}, {%8,%9}, {%0,%1,%2,%3};"
        : "+f"(d[0]), "+f"(d[1]), "+f"(d[2]), "+f"(d[3])
        : "r"(a[0]), "r"(a[1]), "r"(a[2]), "r"(a[3]), "r"(b0), "r"(b1));
}

// ---------------- fp32 -> fp16 convert (x, y activations) -------------------
__global__ __launch_bounds__(256) void cvt_kernel(const float4* __restrict__ in0,
                                                  const float4* __restrict__ in1,
                                                  uint2* __restrict__ o0,
                                                  uint2* __restrict__ o1, int n4)
{
    int i = blockIdx.x * blockDim.x + threadIdx.x;
    if (i >= n4) return;
    const float4* src = blockIdx.y ? in1 : in0;
    uint2* dst = blockIdx.y ? o1 : o0;
    float4 v = src[i];
    uint2 H;
    H.x = (uint32_t)__half_as_ushort(__float2half_rn(v.x)) |
          ((uint32_t)__half_as_ushort(__float2half_rn(v.y)) << 16);
    H.y = (uint32_t)__half_as_ushort(__float2half_rn(v.z)) |
          ((uint32_t)__half_as_ushort(__float2half_rn(v.w)) << 16);
    dst[i] = H;
}

// ---------------- fp32 -> fp16 round (weights, 4 at once) -------------------
__global__ __launch_bounds__(256) void wconv_kernel(const float4* __restrict__ w0,
                                                    const float4* __restrict__ w1,
                                                    const float4* __restrict__ w2,
                                                    const float4* __restrict__ w3,
                                                    uint2* __restrict__ o0,
                                                    uint2* __restrict__ o1,
                                                    uint2* __restrict__ o2,
                                                    uint2* __restrict__ o3, int n4)
{
    int i = blockIdx.x * blockDim.x + threadIdx.x;
    if (i >= n4) return;
    const float4* src = (blockIdx.y == 0) ? w0 : (blockIdx.y == 1) ? w1
                        : (blockIdx.y == 2) ? w2 : w3;
    uint2* dst = (blockIdx.y == 0) ? o0 : (blockIdx.y == 1) ? o1
                 : (blockIdx.y == 2) ? o2 : o3;
    float4 v = src[i];
    uint2 H;
    H.x = (uint32_t)__half_as_ushort(__float2half_rn(v.x)) |
          ((uint32_t)__half_as_ushort(__float2half_rn(v.y)) << 16);
    H.y = (uint32_t)__half_as_ushort(__float2half_rn(v.z)) |
          ((uint32_t)__half_as_ushort(__float2half_rn(v.w)) << 16);
    dst[i] = H;
}

// ---------------- fp16 warp-MMA GEMM (256 threads, BM128 x BN128) ------------
__device__ __forceinline__ void load_stage(uint32_t sbase,
    const __half* __restrict__ A, const __half* __restrict__ B,
    int m0, int n0, int kc, int tid)
{
    const int kcol = kc * BK;
    #pragma unroll
    for (int i = 0; i < 4; ++i) {               // A + B: 128 rows x 8 ch
        int idx = tid + i * 256;
        int row = idx >> 3;
        int ch  = idx & 7;
        uint32_t soff = row * 128 + (((ch ^ (row & 7)) << 4));
        size_t ga = (size_t)(m0 + row) * DIMW + kcol + ch * 8;
        size_t gb = (size_t)(n0 + row) * DIMW + kcol + ch * 8;
        cp16(sbase + soff,            A + ga);
        cp16(sbase + A_TILE_B + soff, B + gb);
    }
    cp_commit();
}

// mode: 1 = fp32 + resid + bias, 2 = fp16 output (psum optional LN partials)
__device__ __forceinline__ void gemm_body(
    const __half* __restrict__ A, const __half* __restrict__ B,
    float* __restrict__ C, __half* __restrict__ C16,
    const float* __restrict__ Yadd, const float* __restrict__ bias, int mode,
    float2* __restrict__ psum)
{
    extern __shared__ char dsm[];
    const uint32_t sb = smem_u32(dsm);

    const int tid  = threadIdx.x;
    const int wid  = tid >> 5;
    const int lane = tid & 31;
    const int warp_m = wid >> 1;      // 0..3 -> 32 rows each
    const int warp_n = wid & 1;       // 0..1 -> 64 cols each
    const int m0 = blockIdx.y * BM;
    const int n0 = blockIdx.x * BN;

    float acc[2][8][4];
    #pragma unroll
    for (int a = 0; a < 2; ++a)
        #pragma unroll
        for (int b = 0; b < 8; ++b)
            #pragma unroll
            for (int c = 0; c < 4; ++c) acc[a][b][c] = 0.f;

    #pragma unroll
    for (int s = 0; s < NSTAGE - 1; ++s)
        load_stage(sb + s * STAGE_B, A, B, m0, n0, s, tid);

    const int frag_row = lane & 15;
    const int frag_ch  = lane >> 4;

    #pragma unroll 1
    for (int kc = 0; kc < NKC; ++kc) {
        cp_wait<NSTAGE - 2>();
        __syncthreads();

        const uint32_t st = sb + (kc % NSTAGE) * STAGE_B;
        const uint32_t sA = st;
        const uint32_t sB = st + A_TILE_B;

        if (kc + NSTAGE - 1 < NKC)
            load_stage(sb + ((kc + NSTAGE - 1) % NSTAGE) * STAGE_B, A, B,
                       m0, n0, kc + NSTAGE - 1, tid);

        #pragma unroll
        for (int kk = 0; kk < 4; ++kk) {
            uint32_t ah[2][4];
            #pragma unroll
            for (int mi = 0; mi < 2; ++mi) {
                int row = warp_m * 32 + mi * 16 + frag_row;
                int ch  = kk * 2 + frag_ch;
                uint32_t off = row * 128 + (((ch ^ (row & 7)) << 4));
                ldsm4(ah[mi], sA + off);
            }
            uint32_t bh[4][4];
            #pragma unroll
            for (int ng = 0; ng < 4; ++ng) {
                int row = warp_n * 64 + ng * 16 + frag_row;
                int ch  = kk * 2 + frag_ch;
                uint32_t off = row * 128 + (((ch ^ (row & 7)) << 4));
                ldsm4(bh[ng], sB + off);
            }
            #pragma unroll
            for (int mi = 0; mi < 2; ++mi)
                #pragma unroll
                for (int ng = 0; ng < 4; ++ng) {
                    mma16816(acc[mi][ng * 2],     ah[mi], bh[ng][0], bh[ng][2]);
                    mma16816(acc[mi][ng * 2 + 1], ah[mi], bh[ng][1], bh[ng][3]);
                }
        }
    }

    const int erow = lane >> 2;
    const int ecol = (lane & 3) * 2;
    #pragma unroll
    for (int mi = 0; mi < 2; ++mi) {
        float s0 = 0.f, q0 = 0.f, s1 = 0.f, q1 = 0.f;
        #pragma unroll
        for (int ni = 0; ni < 8; ++ni) {
            size_t r0 = (size_t)m0 + warp_m * 32 + mi * 16 + erow;
            int    c  = n0 + warp_n * 64 + ni * 8 + ecol;
            float2 v0 = make_float2(acc[mi][ni][0], acc[mi][ni][1]);
            float2 v1 = make_float2(acc[mi][ni][2], acc[mi][ni][3]);
            if (mode == 2) {
                __half2 h0 = __floats2half2_rn(v0.x, v0.y);
                __half2 h1 = __floats2half2_rn(v1.x, v1.y);
                *reinterpret_cast<__half2*>(C16 + r0 * DIMW + c)       = h0;
                *reinterpret_cast<__half2*>(C16 + (r0 + 8) * DIMW + c) = h1;
                if (psum) {
                    float2 f0 = __half22float2(h0);
                    float2 f1 = __half22float2(h1);
                    s0 += f0.x + f0.y; q0 += f0.x * f0.x + f0.y * f0.y;
                    s1 += f1.x + f1.y; q1 += f1.x * f1.x + f1.y * f1.y;
                }
            } else {
                float2 y0 = *(const float2*)(Yadd + r0 * DIMW + c);
                float2 y1 = *(const float2*)(Yadd + (r0 + 8) * DIMW + c);
                float2 bv = *(const float2*)(bias + c);
                v0.x += y0.x + bv.x; v0.y += y0.y + bv.y;
                v1.x += y1.x + bv.x; v1.y += y1.y + bv.y;
                *(float2*)(C + r0 * DIMW + c)       = v0;
                *(float2*)(C + (r0 + 8) * DIMW + c) = v1;
            }
        }
        if (mode == 2 && psum) {
            s0 += __shfl_xor_sync(0xffffffffu, s0, 1);
            s0 += __shfl_xor_sync(0xffffffffu, s0, 2);
            q0 += __shfl_xor_sync(0xffffffffu, q0, 1);
            q0 += __shfl_xor_sync(0xffffffffu, q0, 2);
            s1 += __shfl_xor_sync(0xffffffffu, s1, 1);
            s1 += __shfl_xor_sync(0xffffffffu, s1, 2);
            q1 += __shfl_xor_sync(0xffffffffu, q1, 1);
            q1 += __shfl_xor_sync(0xffffffffu, q1, 2);
            if ((lane & 3) == 0) {
                size_t row = (size_t)m0 + warp_m * 32 + mi * 16 + erow;
                int slot = blockIdx.x * 2 + warp_n;
                psum[row * 8 + slot]       = make_float2(s0, q0);
                psum[(row + 8) * 8 + slot] = make_float2(s1, q1);
            }
        }
    }
}

__global__ __launch_bounds__(256, 2) void qkv_gemm()
{
    if (blockIdx.z == 0)
        gemm_body(g_yh, g_Wq, nullptr, g_qh, nullptr, nullptr, 2, g_psq);
    else if (blockIdx.z == 1)
        gemm_body(g_xh, g_Wk, nullptr, g_kh, nullptr, nullptr, 2, g_psk);
    else
        gemm_body(g_xh, g_Wv, nullptr, g_vh, nullptr, nullptr, 2, nullptr);
}

__global__ __launch_bounds__(256, 2) void out_gemm(const float* __restrict__ y,
                                                   const float* __restrict__ bout,
                                                   float* __restrict__ ynew)
{
    gemm_body(g_oh, g_Wo, ynew, nullptr, y, bout, 1, nullptr);
}

// ---------------- tensor-core windowed attention, 2 blocks/SM ----------------
// Each warp owns 16 rows x all 128 cols; softmax warp-local; P stays in regs
// (QK C-fragments reused directly as PV A-fragments).
#define AQ_OFF   0
#define AK_OFF   16384
#define AVT_OFF  32768
#define ASTQ_OFF 49152
#define ASTK_OFF 50176
#define ASG_OFF  51200
#define ATTN_SMEM 52224
#define TSTRIDE  256

__global__ __launch_bounds__(256, 2) void attn_kernel(
    float* __restrict__ attn_out,
    const float* __restrict__ gq, const float* __restrict__ bq,
    const float* __restrict__ gk, const float* __restrict__ bk)
{
    extern __shared__ char asm_[];
    const uint32_t sb = smem_u32(asm_);
    float2* stq = (float2*)(asm_ + ASTQ_OFF);
    float2* stk = (float2*)(asm_ + ASTK_OFF);
    float*  sgq = (float*)(asm_ + ASG_OFF);
    float*  sbq = sgq + 64;
    float*  sgk = sgq + 128;
    float*  sbk = sgq + 192;

    const int tid = threadIdx.x;
    const int bwh = blockIdx.x;        // bw*8 + h
    const int bw  = bwh >> 3;
    const int h   = bwh & 7;
    const size_t rowbase = (size_t)bw * WIN;
    const int coloff = h * DHEAD;

    if (tid < 128) {
        const float2* pq = g_psq + (rowbase + tid) * 8;
        const float2* pk = g_psk + (rowbase + tid) * 8;
        float s = 0.f, q = 0.f;
        #pragma unroll
        for (int p = 0; p < 8; ++p) { float2 v = pq[p]; s += v.x; q += v.y; }
        float mean = s * (1.f / 512.f);
        float var  = q * (1.f / 512.f) - mean * mean;
        stq[tid] = make_float2(mean, rsqrtf(var + 1e-5f));
        s = 0.f; q = 0.f;
        #pragma unroll
        for (int p = 0; p < 8; ++p) { float2 v = pk[p]; s += v.x; q += v.y; }
        mean = s * (1.f / 512.f);
        var  = q * (1.f / 512.f) - mean * mean;
        stk[tid] = make_float2(mean, rsqrtf(var + 1e-5f));
    } else if (tid < 192) {
        int d = tid - 128;
        sgq[d] = gq[coloff + d] * 0.125f;
        sbq[d] = bq[coloff + d] * 0.125f;
        sgk[d] = gk[coloff + d];
        sbk[d] = bk[coloff + d];
    }
    __syncthreads();

    // ---- load: q,k (fp16 -> LN fp32 -> fp16, swizzled), v -> Vt transposed --
    #pragma unroll
    for (int it = 0; it < 8; ++it) {
        int idx = tid + it * 256;      // 0..2047
        int i   = idx >> 4;            // row 0..127
        int d4  = (idx & 15) << 2;     // 0..60
        size_t goff = (rowbase + i) * DIMW + coloff + d4;
        uint2 qraw = *(const uint2*)(g_qh + goff);
        uint2 kraw = *(const uint2*)(g_kh + goff);
        uint2 vraw = *(const uint2*)(g_vh + goff);

        float2 q01 = __half22float2(*reinterpret_cast<__half2*>(&qraw.x));
        float2 q23 = __half22float2(*reinterpret_cast<__half2*>(&qraw.y));
        float2 k01 = __half22float2(*reinterpret_cast<__half2*>(&kraw.x));
        float2 k23 = __half22float2(*reinterpret_cast<__half2*>(&kraw.y));

        float2 sq_ = stq[i];
        float2 sk_ = stk[i];
        __half2 qh0 = __floats2half2_rn(
            (q01.x - sq_.x) * sq_.y * sgq[d4 + 0] + sbq[d4 + 0],
            (q01.y - sq_.x) * sq_.y * sgq[d4 + 1] + sbq[d4 + 1]);
        __half2 qh1 = __floats2half2_rn(
            (q23.x - sq_.x) * sq_.y * sgq[d4 + 2] + sbq[d4 + 2],
            (q23.y - sq_.x) * sq_.y * sgq[d4 + 3] + sbq[d4 + 3]);
        __half2 kh0 = __floats2half2_rn(
            (k01.x - sk_.x) * sk_.y * sgk[d4 + 0] + sbk[d4 + 0],
            (k01.y - sk_.x) * sk_.y * sgk[d4 + 1] + sbk[d4 + 1]);
        __half2 kh1 = __floats2half2_rn(
            (k23.x - sk_.x) * sk_.y * sgk[d4 + 2] + sbk[d4 + 2],
            (k23.y - sk_.x) * sk_.y * sgk[d4 + 3] + sbk[d4 + 3]);

        uint32_t qkoff = i * 128 + (((d4 >> 3) ^ (i & 7)) << 4) + (d4 & 7) * 2;
        *(__half2*)(asm_ + AQ_OFF + qkoff)     = qh0;
        *(__half2*)(asm_ + AQ_OFF + qkoff + 4) = qh1;
        *(__half2*)(asm_ + AK_OFF + qkoff)     = kh0;
        *(__half2*)(asm_ + AK_OFF + qkoff + 4) = kh1;

        const __half* vh = reinterpret_cast<const __half*>(&vraw);
        #pragma unroll
        for (int w = 0; w < 4; ++w) {
            int d = d4 + w;
            uint32_t off = d * TSTRIDE + (((i >> 3) ^ (d & 7)) << 4) + (i & 7) * 2;
            *(__half*)(asm_ + AVT_OFF + off) = vh[w];
        }
    }
    __syncthreads();

    const int wid  = tid >> 5;
    const int lane = tid & 31;
    const int frag_row = lane & 15;
    const int frag_ch  = lane >> 4;
    const int erow = lane >> 2;
    const int equad = lane & 3;
    const int r0w = wid * 16;          // warp's 16-row slice

    // ---- QK^T via HMMA: acc[ni][4] covers rows r0w..+16, cols ni*8..+8 ------
    float acc[16][4];
    #pragma unroll
    for (int b = 0; b < 16; ++b)
        #pragma unroll
        for (int c = 0; c < 4; ++c) acc[b][c] = 0.f;

    #pragma unroll
    for (int kk = 0; kk < 4; ++kk) {
        uint32_t a[4];
        {
            int row = r0w + frag_row;
            int ch  = kk * 2 + frag_ch;
            ldsm4(a, sb + AQ_OFF + row * 128 + (((ch ^ (row & 7)) << 4)));
        }
        uint32_t bh[8][4];
        #pragma unroll
        for (int ng = 0; ng < 8; ++ng) {
            int row = ng * 16 + frag_row;
            int ch  = kk * 2 + frag_ch;
            ldsm4(bh[ng], sb + AK_OFF + row * 128 + (((ch ^ (row & 7)) << 4)));
        }
        #pragma unroll
        for (int ng = 0; ng < 8; ++ng) {
            mma16816(acc[ng * 2],     a, bh[ng][0], bh[ng][2]);
            mma16816(acc[ng * 2 + 1], a, bh[ng][1], bh[ng][3]);
        }
    }

    // ---- warp-local softmax + write attn (fp32) -----------------------------
    const size_t abase = (size_t)bwh * WIN * WIN;
    #pragma unroll
    for (int hh = 0; hh < 2; ++hh) {
        float m = -1e30f;
        #pragma unroll
        for (int ni = 0; ni < 16; ++ni) {
            m = fmaxf(m, acc[ni][hh * 2]);
            m = fmaxf(m, acc[ni][hh * 2 + 1]);
        }
        m = fmaxf(m, __shfl_xor_sync(0xffffffffu, m, 1));
        m = fmaxf(m, __shfl_xor_sync(0xffffffffu, m, 2));
        float s = 0.f;
        #pragma unroll
        for (int ni = 0; ni < 16; ++ni) {
            float e0 = __expf(acc[ni][hh * 2]     - m);
            float e1 = __expf(acc[ni][hh * 2 + 1] - m);
            acc[ni][hh * 2]     = e0;
            acc[ni][hh * 2 + 1] = e1;
            s += e0 + e1;
        }
        s += __shfl_xor_sync(0xffffffffu, s, 1);
        s += __shfl_xor_sync(0xffffffffu, s, 2);
        float inv = 1.0f / s;
        int row = r0w + hh * 8 + erow;
        #pragma unroll
        for (int ni = 0; ni < 16; ++ni) {
            float p0 = acc[ni][hh * 2]     * inv;
            float p1 = acc[ni][hh * 2 + 1] * inv;
            acc[ni][hh * 2]     = p0;
            acc[ni][hh * 2 + 1] = p1;
            *(float2*)(attn_out + abase + (size_t)row * WIN + ni * 8 + equad * 2) =
                make_float2(p0, p1);
        }
    }

    // ---- convert P fragments to fp16 A-fragments (register-only) ------------
    uint32_t ph[16][2];
    #pragma unroll
    for (int ni = 0; ni < 16; ++ni) {
        __half2 lo = __floats2half2_rn(acc[ni][0], acc[ni][1]);
        __half2 hi = __floats2half2_rn(acc[ni][2], acc[ni][3]);
        ph[ni][0] = *reinterpret_cast<uint32_t*>(&lo);
        ph[ni][1] = *reinterpret_cast<uint32_t*>(&hi);
    }

    // ---- P @ V via HMMA: A from registers, B (Vt) via ldmatrix --------------
    float oac[8][4];
    #pragma unroll
    for (int b = 0; b < 8; ++b)
        #pragma unroll
        for (int c = 0; c < 4; ++c) oac[b][c] = 0.f;

    #pragma unroll
    for (int kk = 0; kk < 8; ++kk) {
        uint32_t ap[4] = { ph[kk * 2][0], ph[kk * 2][1],
                           ph[kk * 2 + 1][0], ph[kk * 2 + 1][1] };
        uint32_t bv[4][4];
        #pragma unroll
        for (int ng = 0; ng < 4; ++ng) {
            int d  = ng * 16 + frag_row;
            int ch = kk * 2 + frag_ch;
            ldsm4(bv[ng], sb + AVT_OFF + d * TSTRIDE + (((ch ^ (d & 7)) << 4)));
        }
        #pragma unroll
        for (int ng = 0; ng < 4; ++ng) {
            mma16816(oac[ng * 2],     ap, bv[ng][0], bv[ng][2]);
            mma16816(oac[ng * 2 + 1], ap, bv[ng][1], bv[ng][3]);
        }
    }

    // ---- write o (fp16) -----------------------------------------------------
    #pragma unroll
    for (int ni = 0; ni < 8; ++ni) {
        int r0 = r0w + erow;
        int c  = coloff + ni * 8 + equad * 2;
        size_t go0 = (rowbase + r0) * DIMW + c;
        size_t go1 = (rowbase + r0 + 8) * DIMW + c;
        *(__half2*)(g_oh + go0) = __floats2half2_rn(oac[ni][0], oac[ni][1]);
        *(__half2*)(g_oh + go1) = __floats2half2_rn(oac[ni][2], oac[ni][3]);
    }
}

// ---------------- launcher ---------------------------------------------------
extern "C" void kernel_launch(void* const* d_in, const int* in_sizes, int n_in,
                              void* d_out, int out_size)
{
    const float* x  = (const float*)d_in[0];
    const float* y  = (const float*)d_in[1];
    const float* Wq = (const float*)d_in[2];
    const float* gq = (const float*)d_in[3];
    const float* bq = (const float*)d_in[4];
    const float* Wk = (const float*)d_in[5];
    const float* gk = (const float*)d_in[6];
    const float* bk = (const float*)d_in[7];
    const float* Wv = (const float*)d_in[8];
    const float* Wo = (const float*)d_in[9];
    const float* bo = (const float*)d_in[10];

    float* ynew = (float*)d_out;
    float* attn = ynew + (size_t)M_TOT * DIMW;

    void *p_xh, *p_yh;
    void *p_wq, *p_wk, *p_wv, *p_wo;
    cudaGetSymbolAddress(&p_xh, g_xh);  cudaGetSymbolAddress(&p_yh, g_yh);
    cudaGetSymbolAddress(&p_wq, g_Wq);  cudaGetSymbolAddress(&p_wk, g_Wk);
    cudaGetSymbolAddress(&p_wv, g_Wv);  cudaGetSymbolAddress(&p_wo, g_Wo);

    cudaFuncSetAttribute(attn_kernel,
                         cudaFuncAttributeMaxDynamicSharedMemorySize, ATTN_SMEM);
    cudaFuncSetAttribute(qkv_gemm,
                         cudaFuncAttributeMaxDynamicSharedMemorySize, GEMM_SMEM);
    cudaFuncSetAttribute(out_gemm,
                         cudaFuncAttributeMaxDynamicSharedMemorySize, GEMM_SMEM);

    // 1) convert activations and weights to fp16
    const int n4_act = (M_TOT * DIMW) / 4;
    const int n4_w   = (DIMW * DIMW) / 4;
    cvt_kernel<<<dim3((n4_act + 255) / 256, 2), 256>>>(
        (const float4*)x, (const float4*)y, (uint2*)p_xh, (uint2*)p_yh, n4_act);
    wconv_kernel<<<dim3((n4_w + 255) / 256, 4), 256>>>(
        (const float4*)Wq, (const float4*)Wk, (const float4*)Wv, (const float4*)Wo,
        (uint2*)p_wq, (uint2*)p_wk, (uint2*)p_wv, (uint2*)p_wo, n4_w);

    // 2) q/k/v projections (fp16 warp-MMA; LN partial sums fused in epilogue)
    qkv_gemm<<<dim3(DIMW / BN, M_TOT / BM, 3), 256, GEMM_SMEM>>>();

    // 3) tensor-core windowed attention (stats combined from partials)
    attn_kernel<<<4096, 256, ATTN_SMEM>>>(attn, gq, bq, gk, bk);

    // 4) final projection with residual epilogue
    out_gemm<<<dim3(DIMW / BN, M_TOT / BM), 256, GEMM_SMEM>>>(y, bo, ynew);
}

// round 17
// speedup vs baseline: 1.0613x; 1.0263x over previous
#include <cuda_runtime.h>
#include <cuda_fp16.h>
#include <cstdint>

#define M_TOT 65536      // B*N rows
#define DIMW  512        // DIM == INNER
#define WIN   128
#define NHEAD 8
#define DHEAD 64

// GEMM tiling (warp-MMA, mma.sync m16n8k16 fp16), 256 thr, 2 CTA/SM
#define BM 128
#define BN 128
#define BK 64
#define NKC (DIMW / BK)
#define A_TILE_B (BM * 128)                     // 16 KB
#define B_TILE_B (BN * 128)                     // 16 KB
#define STAGE_B (A_TILE_B + B_TILE_B)           // 32 KB
#define NSTAGE 3
#define GEMM_SMEM (NSTAGE * STAGE_B)            // 96 KB

// ---------------- scratch (__device__ globals; no allocation allowed) -------
__device__ __half g_qh[(size_t)M_TOT * DIMW];
__device__ __half g_kh[(size_t)M_TOT * DIMW];
__device__ __half g_vh[(size_t)M_TOT * DIMW];
__device__ __half g_oh[(size_t)M_TOT * DIMW];

__device__ __half g_xh[(size_t)M_TOT * DIMW];
__device__ __half g_yh[(size_t)M_TOT * DIMW];

// per-row LN partial sums: 8 slots/row (4 n-tiles x 2 warp_n), (sum, sumsq)
__device__ float2 g_psq[(size_t)M_TOT * 8];
__device__ float2 g_psk[(size_t)M_TOT * 8];

__device__ __half g_Wq[DIMW * DIMW];
__device__ __half g_Wk[DIMW * DIMW];
__device__ __half g_Wv[DIMW * DIMW];
__device__ __half g_Wo[DIMW * DIMW];

// ---------------- small asm helpers ------------------------------------------
__device__ __forceinline__ uint32_t smem_u32(const void* p) {
    uint32_t a;
    asm("{ .reg .u64 t; cvta.to.shared.u64 t, %1; cvt.u32.u64 %0, t; }"
        : "=r"(a) : "l"(p));
    return a;
}
__device__ __forceinline__ void cp16(uint32_t dst, const void* src) {
    asm volatile("cp.async.cg.shared.global [%0], [%1], 16;"
                 :: "r"(dst), "l"(src) : "memory");
}
__device__ __forceinline__ void cp_commit() {
    asm volatile("cp.async.commit_group;" ::: "memory");
}
template <int N>
__device__ __forceinline__ void cp_wait() {
    asm volatile("cp.async.wait_group %0;" :: "n"(N) : "memory");
}
__device__ __forceinline__ void ldsm4(uint32_t* r, uint32_t addr) {
    asm volatile("ldmatrix.sync.aligned.m8n8.x4.shared.b16 {%0,%1,%2,%3}, [%4];"
                 : "=r"(r[0]), "=r"(r[1]), "=r"(r[2]), "=r"(r[3]) : "r"(addr));
}
__device__ __forceinline__ void ldsm4t(uint32_t* r, uint32_t addr) {
    asm volatile("ldmatrix.sync.aligned.m8n8.x4.trans.shared.b16 {%0,%1,%2,%3}, [%4];"
                 : "=r"(r[0]), "=r"(r[1]), "=r"(r[2]), "=r"(r[3]) : "r"(addr));
}
__device__ __forceinline__ void mma16816(float* d, const uint32_t* a,
                                         uint32_t b0, uint32_t b1) {
    asm volatile(
        "mma.sync.aligned.m16n8k16.row.col.f32.f16.f16.f32 "
        "{%0,%1,%2,%3}, {%4,%5,%6,%7}, {%8,%9}, {%0,%1,%2,%3};"
        : "+f"(d[0]), "+f"(d[1]), "+f"(d[2]), "+f"(d[3])
        : "r"(a[0]), "r"(a[1]), "r"(a[2]), "r"(a[3]), "r"(b0), "r"(b1));
}

// ---------------- fp32 -> fp16 convert (x, y activations) -------------------
__global__ __launch_bounds__(256) void cvt_kernel(const float4* __restrict__ in0,
                                                  const float4* __restrict__ in1,
                                                  uint2* __restrict__ o0,
                                                  uint2* __restrict__ o1, int n4)
{
    int i = blockIdx.x * blockDim.x + threadIdx.x;
    if (i >= n4) return;
    const float4* src = blockIdx.y ? in1 : in0;
    uint2* dst = blockIdx.y ? o1 : o0;
    float4 v = src[i];
    uint2 H;
    H.x = (uint32_t)__half_as_ushort(__float2half_rn(v.x)) |
          ((uint32_t)__half_as_ushort(__float2half_rn(v.y)) << 16);
    H.y = (uint32_t)__half_as_ushort(__float2half_rn(v.z)) |
          ((uint32_t)__half_as_ushort(__float2half_rn(v.w)) << 16);
    dst[i] = H;
}

// ---------------- fp32 -> fp16 round (weights, 4 at once) -------------------
__global__ __launch_bounds__(256) void wconv_kernel(const float4* __restrict__ w0,
                                                    const float4* __restrict__ w1,
                                                    const float4* __restrict__ w2,
                                                    const float4* __restrict__ w3,
                                                    uint2* __restrict__ o0,
                                                    uint2* __restrict__ o1,
                                                    uint2* __restrict__ o2,
                                                    uint2* __restrict__ o3, int n4)
{
    int i = blockIdx.x * blockDim.x + threadIdx.x;
    if (i >= n4) return;
    const float4* src = (blockIdx.y == 0) ? w0 : (blockIdx.y == 1) ? w1
                        : (blockIdx.y == 2) ? w2 : w3;
    uint2* dst = (blockIdx.y == 0) ? o0 : (blockIdx.y == 1) ? o1
                 : (blockIdx.y == 2) ? o2 : o3;
    float4 v = src[i];
    uint2 H;
    H.x = (uint32_t)__half_as_ushort(__float2half_rn(v.x)) |
          ((uint32_t)__half_as_ushort(__float2half_rn(v.y)) << 16);
    H.y = (uint32_t)__half_as_ushort(__float2half_rn(v.z)) |
          ((uint32_t)__half_as_ushort(__float2half_rn(v.w)) << 16);
    dst[i] = H;
}

// ---------------- fp16 warp-MMA GEMM (256 threads, BM128 x BN128) ------------
__device__ __forceinline__ void load_stage(uint32_t sbase,
    const __half* __restrict__ A, const __half* __restrict__ B,
    int m0, int n0, int kc, int tid)
{
    const int kcol = kc * BK;
    #pragma unroll
    for (int i = 0; i < 4; ++i) {               // A + B: 128 rows x 8 ch
        int idx = tid + i * 256;
        int row = idx >> 3;
        int ch  = idx & 7;
        uint32_t soff = row * 128 + (((ch ^ (row & 7)) << 4));
        size_t ga = (size_t)(m0 + row) * DIMW + kcol + ch * 8;
        size_t gb = (size_t)(n0 + row) * DIMW + kcol + ch * 8;
        cp16(sbase + soff,            A + ga);
        cp16(sbase + A_TILE_B + soff, B + gb);
    }
    cp_commit();
}

// mode: 1 = fp32 + resid + bias, 2 = fp16 output (psum optional LN partials)
__device__ __forceinline__ void gemm_body(
    const __half* __restrict__ A, const __half* __restrict__ B,
    float* __restrict__ C, __half* __restrict__ C16,
    const float* __restrict__ Yadd, const float* __restrict__ bias, int mode,
    float2* __restrict__ psum)
{
    extern __shared__ char dsm[];
    const uint32_t sb = smem_u32(dsm);

    const int tid  = threadIdx.x;
    const int wid  = tid >> 5;
    const int lane = tid & 31;
    const int warp_m = wid >> 1;      // 0..3 -> 32 rows each
    const int warp_n = wid & 1;       // 0..1 -> 64 cols each
    const int m0 = blockIdx.y * BM;
    const int n0 = blockIdx.x * BN;

    float acc[2][8][4];
    #pragma unroll
    for (int a = 0; a < 2; ++a)
        #pragma unroll
        for (int b = 0; b < 8; ++b)
            #pragma unroll
            for (int c = 0; c < 4; ++c) acc[a][b][c] = 0.f;

    #pragma unroll
    for (int s = 0; s < NSTAGE - 1; ++s)
        load_stage(sb + s * STAGE_B, A, B, m0, n0, s, tid);

    const int frag_row = lane & 15;
    const int frag_ch  = lane >> 4;

    #pragma unroll 1
    for (int kc = 0; kc < NKC; ++kc) {
        cp_wait<NSTAGE - 2>();
        __syncthreads();

        const uint32_t st = sb + (kc % NSTAGE) * STAGE_B;
        const uint32_t sA = st;
        const uint32_t sB = st + A_TILE_B;

        if (kc + NSTAGE - 1 < NKC)
            load_stage(sb + ((kc + NSTAGE - 1) % NSTAGE) * STAGE_B, A, B,
                       m0, n0, kc + NSTAGE - 1, tid);

        #pragma unroll
        for (int kk = 0; kk < 4; ++kk) {
            uint32_t ah[2][4];
            #pragma unroll
            for (int mi = 0; mi < 2; ++mi) {
                int row = warp_m * 32 + mi * 16 + frag_row;
                int ch  = kk * 2 + frag_ch;
                uint32_t off = row * 128 + (((ch ^ (row & 7)) << 4));
                ldsm4(ah[mi], sA + off);
            }
            uint32_t bh[4][4];
            #pragma unroll
            for (int ng = 0; ng < 4; ++ng) {
                int row = warp_n * 64 + ng * 16 + frag_row;
                int ch  = kk * 2 + frag_ch;
                uint32_t off = row * 128 + (((ch ^ (row & 7)) << 4));
                ldsm4(bh[ng], sB + off);
            }
            #pragma unroll
            for (int mi = 0; mi < 2; ++mi)
                #pragma unroll
                for (int ng = 0; ng < 4; ++ng) {
                    mma16816(acc[mi][ng * 2],     ah[mi], bh[ng][0], bh[ng][2]);
                    mma16816(acc[mi][ng * 2 + 1], ah[mi], bh[ng][1], bh[ng][3]);
                }
        }
    }

    const int erow = lane >> 2;
    const int ecol = (lane & 3) * 2;
    #pragma unroll
    for (int mi = 0; mi < 2; ++mi) {
        float s0 = 0.f, q0 = 0.f, s1 = 0.f, q1 = 0.f;
        #pragma unroll
        for (int ni = 0; ni < 8; ++ni) {
            size_t r0 = (size_t)m0 + warp_m * 32 + mi * 16 + erow;
            int    c  = n0 + warp_n * 64 + ni * 8 + ecol;
            float2 v0 = make_float2(acc[mi][ni][0], acc[mi][ni][1]);
            float2 v1 = make_float2(acc[mi][ni][2], acc[mi][ni][3]);
            if (mode == 2) {
                __half2 h0 = __floats2half2_rn(v0.x, v0.y);
                __half2 h1 = __floats2half2_rn(v1.x, v1.y);
                *reinterpret_cast<__half2*>(C16 + r0 * DIMW + c)       = h0;
                *reinterpret_cast<__half2*>(C16 + (r0 + 8) * DIMW + c) = h1;
                if (psum) {
                    float2 f0 = __half22float2(h0);
                    float2 f1 = __half22float2(h1);
                    s0 += f0.x + f0.y; q0 += f0.x * f0.x + f0.y * f0.y;
                    s1 += f1.x + f1.y; q1 += f1.x * f1.x + f1.y * f1.y;
                }
            } else {
                float2 y0 = *(const float2*)(Yadd + r0 * DIMW + c);
                float2 y1 = *(const float2*)(Yadd + (r0 + 8) * DIMW + c);
                float2 bv = *(const float2*)(bias + c);
                v0.x += y0.x + bv.x; v0.y += y0.y + bv.y;
                v1.x += y1.x + bv.x; v1.y += y1.y + bv.y;
                *(float2*)(C + r0 * DIMW + c)       = v0;
                *(float2*)(C + (r0 + 8) * DIMW + c) = v1;
            }
        }
        if (mode == 2 && psum) {
            s0 += __shfl_xor_sync(0xffffffffu, s0, 1);
            s0 += __shfl_xor_sync(0xffffffffu, s0, 2);
            q0 += __shfl_xor_sync(0xffffffffu, q0, 1);
            q0 += __shfl_xor_sync(0xffffffffu, q0, 2);
            s1 += __shfl_xor_sync(0xffffffffu, s1, 1);
            s1 += __shfl_xor_sync(0xffffffffu, s1, 2);
            q1 += __shfl_xor_sync(0xffffffffu, q1, 1);
            q1 += __shfl_xor_sync(0xffffffffu, q1, 2);
            if ((lane & 3) == 0) {
                size_t row = (size_t)m0 + warp_m * 32 + mi * 16 + erow;
                int slot = blockIdx.x * 2 + warp_n;
                psum[row * 8 + slot]       = make_float2(s0, q0);
                psum[(row + 8) * 8 + slot] = make_float2(s1, q1);
            }
        }
    }
}

__global__ __launch_bounds__(256, 2) void qkv_gemm()
{
    if (blockIdx.z == 0)
        gemm_body(g_yh, g_Wq, nullptr, g_qh, nullptr, nullptr, 2, g_psq);
    else if (blockIdx.z == 1)
        gemm_body(g_xh, g_Wk, nullptr, g_kh, nullptr, nullptr, 2, g_psk);
    else
        gemm_body(g_xh, g_Wv, nullptr, g_vh, nullptr, nullptr, 2, nullptr);
}

__global__ __launch_bounds__(256, 2) void out_gemm(const float* __restrict__ y,
                                                   const float* __restrict__ bout,
                                                   float* __restrict__ ynew)
{
    gemm_body(g_oh, g_Wo, ynew, nullptr, y, bout, 1, nullptr);
}

// ---------------- tensor-core windowed attention, 2 blocks/SM ----------------
// Warp owns 16 rows x all 128 cols; softmax warp-local; P stays in registers;
// V stored naturally [j][d] and loaded for PV via ldmatrix.trans.
#define AQ_OFF   0
#define AK_OFF   16384
#define AV_OFF   32768
#define ASTQ_OFF 49152
#define ASTK_OFF 50176
#define ASG_OFF  51200
#define ATTN_SMEM 52224

__global__ __launch_bounds__(256, 2) void attn_kernel(
    float* __restrict__ attn_out,
    const float* __restrict__ gq, const float* __restrict__ bq,
    const float* __restrict__ gk, const float* __restrict__ bk)
{
    extern __shared__ char asm_[];
    const uint32_t sb = smem_u32(asm_);
    float2* stq = (float2*)(asm_ + ASTQ_OFF);
    float2* stk = (float2*)(asm_ + ASTK_OFF);
    float*  sgq = (float*)(asm_ + ASG_OFF);
    float*  sbq = sgq + 64;
    float*  sgk = sgq + 128;
    float*  sbk = sgq + 192;

    const int tid = threadIdx.x;
    const int bwh = blockIdx.x;        // bw*8 + h
    const int bw  = bwh >> 3;
    const int h   = bwh & 7;
    const size_t rowbase = (size_t)bw * WIN;
    const int coloff = h * DHEAD;

    if (tid < 128) {
        const float2* pq = g_psq + (rowbase + tid) * 8;
        const float2* pk = g_psk + (rowbase + tid) * 8;
        float s = 0.f, q = 0.f;
        #pragma unroll
        for (int p = 0; p < 8; ++p) { float2 v = pq[p]; s += v.x; q += v.y; }
        float mean = s * (1.f / 512.f);
        float var  = q * (1.f / 512.f) - mean * mean;
        stq[tid] = make_float2(mean, rsqrtf(var + 1e-5f));
        s = 0.f; q = 0.f;
        #pragma unroll
        for (int p = 0; p < 8; ++p) { float2 v = pk[p]; s += v.x; q += v.y; }
        mean = s * (1.f / 512.f);
        var  = q * (1.f / 512.f) - mean * mean;
        stk[tid] = make_float2(mean, rsqrtf(var + 1e-5f));
    } else if (tid < 192) {
        int d = tid - 128;
        sgq[d] = gq[coloff + d] * 0.125f;
        sbq[d] = bq[coloff + d] * 0.125f;
        sgk[d] = gk[coloff + d];
        sbk[d] = bk[coloff + d];
    }
    __syncthreads();

    // ---- load: q,k (fp16 -> LN fp32 -> fp16, swizzled), v natural -----------
    #pragma unroll
    for (int it = 0; it < 8; ++it) {
        int idx = tid + it * 256;      // 0..2047
        int i   = idx >> 4;            // row 0..127
        int d4  = (idx & 15) << 2;     // 0..60
        size_t goff = (rowbase + i) * DIMW + coloff + d4;
        uint2 qraw = *(const uint2*)(g_qh + goff);
        uint2 kraw = *(const uint2*)(g_kh + goff);
        uint2 vraw = *(const uint2*)(g_vh + goff);

        float2 q01 = __half22float2(*reinterpret_cast<__half2*>(&qraw.x));
        float2 q23 = __half22float2(*reinterpret_cast<__half2*>(&qraw.y));
        float2 k01 = __half22float2(*reinterpret_cast<__half2*>(&kraw.x));
        float2 k23 = __half22float2(*reinterpret_cast<__half2*>(&kraw.y));

        float2 sq_ = stq[i];
        float2 sk_ = stk[i];
        __half2 qh0 = __floats2half2_rn(
            (q01.x - sq_.x) * sq_.y * sgq[d4 + 0] + sbq[d4 + 0],
            (q01.y - sq_.x) * sq_.y * sgq[d4 + 1] + sbq[d4 + 1]);
        __half2 qh1 = __floats2half2_rn(
            (q23.x - sq_.x) * sq_.y * sgq[d4 + 2] + sbq[d4 + 2],
            (q23.y - sq_.x) * sq_.y * sgq[d4 + 3] + sbq[d4 + 3]);
        __half2 kh0 = __floats2half2_rn(
            (k01.x - sk_.x) * sk_.y * sgk[d4 + 0] + sbk[d4 + 0],
            (k01.y - sk_.x) * sk_.y * sgk[d4 + 1] + sbk[d4 + 1]);
        __half2 kh1 = __floats2half2_rn(
            (k23.x - sk_.x) * sk_.y * sgk[d4 + 2] + sbk[d4 + 2],
            (k23.y - sk_.x) * sk_.y * sgk[d4 + 3] + sbk[d4 + 3]);

        uint32_t qkoff = i * 128 + (((d4 >> 3) ^ (i & 7)) << 4) + (d4 & 7) * 2;
        *(__half2*)(asm_ + AQ_OFF + qkoff)     = qh0;
        *(__half2*)(asm_ + AQ_OFF + qkoff + 4) = qh1;
        *(__half2*)(asm_ + AK_OFF + qkoff)     = kh0;
        *(__half2*)(asm_ + AK_OFF + qkoff + 4) = kh1;
        *(uint2*)(asm_ + AV_OFF + qkoff)       = vraw;   // natural [j][d]
    }
    __syncthreads();

    const int wid  = tid >> 5;
    const int lane = tid & 31;
    const int frag_row = lane & 15;
    const int frag_ch  = lane >> 4;
    const int erow = lane >> 2;
    const int equad = lane & 3;
    const int r0w = wid * 16;          // warp's 16-row slice

    // ---- QK^T via HMMA: acc[ni][4] covers rows r0w..+16, cols ni*8..+8 ------
    float acc[16][4];
    #pragma unroll
    for (int b = 0; b < 16; ++b)
        #pragma unroll
        for (int c = 0; c < 4; ++c) acc[b][c] = 0.f;

    #pragma unroll
    for (int kk = 0; kk < 4; ++kk) {
        uint32_t a[4];
        {
            int row = r0w + frag_row;
            int ch  = kk * 2 + frag_ch;
            ldsm4(a, sb + AQ_OFF + row * 128 + (((ch ^ (row & 7)) << 4)));
        }
        uint32_t bh[8][4];
        #pragma unroll
        for (int ng = 0; ng < 8; ++ng) {
            int row = ng * 16 + frag_row;
            int ch  = kk * 2 + frag_ch;
            ldsm4(bh[ng], sb + AK_OFF + row * 128 + (((ch ^ (row & 7)) << 4)));
        }
        #pragma unroll
        for (int ng = 0; ng < 8; ++ng) {
            mma16816(acc[ng * 2],     a, bh[ng][0], bh[ng][2]);
            mma16816(acc[ng * 2 + 1], a, bh[ng][1], bh[ng][3]);
        }
    }

    // ---- warp-local softmax + write attn (fp32) -----------------------------
    const size_t abase = (size_t)bwh * WIN * WIN;
    #pragma unroll
    for (int hh = 0; hh < 2; ++hh) {
        float m = -1e30f;
        #pragma unroll
        for (int ni = 0; ni < 16; ++ni) {
            m = fmaxf(m, acc[ni][hh * 2]);
            m = fmaxf(m, acc[ni][hh * 2 + 1]);
        }
        m = fmaxf(m, __shfl_xor_sync(0xffffffffu, m, 1));
        m = fmaxf(m, __shfl_xor_sync(0xffffffffu, m, 2));
        float s = 0.f;
        #pragma unroll
        for (int ni = 0; ni < 16; ++ni) {
            float e0 = __expf(acc[ni][hh * 2]     - m);
            float e1 = __expf(acc[ni][hh * 2 + 1] - m);
            acc[ni][hh * 2]     = e0;
            acc[ni][hh * 2 + 1] = e1;
            s += e0 + e1;
        }
        s += __shfl_xor_sync(0xffffffffu, s, 1);
        s += __shfl_xor_sync(0xffffffffu, s, 2);
        float inv = 1.0f / s;
        int row = r0w + hh * 8 + erow;
        #pragma unroll
        for (int ni = 0; ni < 16; ++ni) {
            float p0 = acc[ni][hh * 2]     * inv;
            float p1 = acc[ni][hh * 2 + 1] * inv;
            acc[ni][hh * 2]     = p0;
            acc[ni][hh * 2 + 1] = p1;
            *(float2*)(attn_out + abase + (size_t)row * WIN + ni * 8 + equad * 2) =
                make_float2(p0, p1);
        }
    }

    // ---- convert P fragments to fp16 A-fragments (register-only) ------------
    uint32_t ph[16][2];
    #pragma unroll
    for (int ni = 0; ni < 16; ++ni) {
        __half2 lo = __floats2half2_rn(acc[ni][0], acc[ni][1]);
        __half2 hi = __floats2half2_rn(acc[ni][2], acc[ni][3]);
        ph[ni][0] = *reinterpret_cast<uint32_t*>(&lo);
        ph[ni][1] = *reinterpret_cast<uint32_t*>(&hi);
    }

    // ---- P @ V via HMMA: A from registers, B via ldmatrix.trans on V[j][d] --
    float oac[8][4];
    #pragma unroll
    for (int b = 0; b < 8; ++b)
        #pragma unroll
        for (int c = 0; c < 4; ++c) oac[b][c] = 0.f;

    #pragma unroll
    for (int kk = 0; kk < 8; ++kk) {
        uint32_t ap[4] = { ph[kk * 2][0], ph[kk * 2][1],
                           ph[kk * 2 + 1][0], ph[kk * 2 + 1][1] };
        uint32_t bv[4][4];
        #pragma unroll
        for (int ngp = 0; ngp < 4; ++ngp) {      // each covers 2 d-tiles
            int row = kk * 16 + frag_row;        // j
            int ch  = ngp * 2 + frag_ch;         // d chunk
            ldsm4t(bv[ngp], sb + AV_OFF + row * 128 + (((ch ^ (row & 7)) << 4)));
        }
        #pragma unroll
        for (int ngp = 0; ngp < 4; ++ngp) {
            // m0/m1 = b0/b1 of d-tile 2*ngp; m2/m3 = b0/b1 of d-tile 2*ngp+1
            mma16816(oac[ngp * 2],     ap, bv[ngp][0], bv[ngp][1]);
            mma16816(oac[ngp * 2 + 1], ap, bv[ngp][2], bv[ngp][3]);
        }
    }

    // ---- write o (fp16) -----------------------------------------------------
    #pragma unroll
    for (int ni = 0; ni < 8; ++ni) {
        int r0 = r0w + erow;
        int c  = coloff + ni * 8 + equad * 2;
        size_t go0 = (rowbase + r0) * DIMW + c;
        size_t go1 = (rowbase + r0 + 8) * DIMW + c;
        *(__half2*)(g_oh + go0) = __floats2half2_rn(oac[ni][0], oac[ni][1]);
        *(__half2*)(g_oh + go1) = __floats2half2_rn(oac[ni][2], oac[ni][3]);
    }
}

// ---------------- launcher ---------------------------------------------------
extern "C" void kernel_launch(void* const* d_in, const int* in_sizes, int n_in,
                              void* d_out, int out_size)
{
    const float* x  = (const float*)d_in[0];
    const float* y  = (const float*)d_in[1];
    const float* Wq = (const float*)d_in[2];
    const float* gq = (const float*)d_in[3];
    const float* bq = (const float*)d_in[4];
    const float* Wk = (const float*)d_in[5];
    const float* gk = (const float*)d_in[6];
    const float* bk = (const float*)d_in[7];
    const float* Wv = (const float*)d_in[8];
    const float* Wo = (const float*)d_in[9];
    const float* bo = (const float*)d_in[10];

    float* ynew = (float*)d_out;
    float* attn = ynew + (size_t)M_TOT * DIMW;

    void *p_xh, *p_yh;
    void *p_wq, *p_wk, *p_wv, *p_wo;
    cudaGetSymbolAddress(&p_xh, g_xh);  cudaGetSymbolAddress(&p_yh, g_yh);
    cudaGetSymbolAddress(&p_wq, g_Wq);  cudaGetSymbolAddress(&p_wk, g_Wk);
    cudaGetSymbolAddress(&p_wv, g_Wv);  cudaGetSymbolAddress(&p_wo, g_Wo);

    cudaFuncSetAttribute(attn_kernel,
                         cudaFuncAttributeMaxDynamicSharedMemorySize, ATTN_SMEM);
    cudaFuncSetAttribute(qkv_gemm,
                         cudaFuncAttributeMaxDynamicSharedMemorySize, GEMM_SMEM);
    cudaFuncSetAttribute(out_gemm,
                         cudaFuncAttributeMaxDynamicSharedMemorySize, GEMM_SMEM);

    // 1) convert activations and weights to fp16
    const int n4_act = (M_TOT * DIMW) / 4;
    const int n4_w   = (DIMW * DIMW) / 4;
    cvt_kernel<<<dim3((n4_act + 255) / 256, 2), 256>>>(
        (const float4*)x, (const float4*)y, (uint2*)p_xh, (uint2*)p_yh, n4_act);
    wconv_kernel<<<dim3((n4_w + 255) / 256, 4), 256>>>(
        (const float4*)Wq, (const float4*)Wk, (const float4*)Wv, (const float4*)Wo,
        (uint2*)p_wq, (uint2*)p_wk, (uint2*)p_wv, (uint2*)p_wo, n4_w);

    // 2) q/k/v projections (fp16 warp-MMA; LN partial sums fused in epilogue)
    qkv_gemm<<<dim3(DIMW / BN, M_TOT / BM, 3), 256, GEMM_SMEM>>>();

    // 3) tensor-core windowed attention (stats combined from partials)
    attn_kernel<<<4096, 256, ATTN_SMEM>>>(attn, gq, bq, gk, bk);

    // 4) final projection with residual epilogue
    out_gemm<<<dim3(DIMW / BN, M_TOT / BM), 256, GEMM_SMEM>>>(y, bo, ynew);
}